// round 7
// baseline (speedup 1.0000x reference)
#include <cuda_runtime.h>
#include <math.h>
#include <stdint.h>

#define SQ   2048
#define HID  1024
#define NH   16
#define HD   64
#define H3   3072
#define NE   8
#define TK   2
#define FF   2048

// ---------------- scratch ----------------
__device__ float g_hn   [SQ*HID];
__device__ float g_qkv  [SQ*H3];
__device__ float g_attn [SQ*HID];
__device__ float g_x1   [SQ*HID];
__device__ float g_hn2  [SQ*HID];
__device__ int   g_topi [SQ*TK];
__device__ float g_topw [SQ*TK];
__device__ int   g_tok  [NE*SQ];
__device__ float g_gate [NE*SQ];
__device__ int   g_slot [NE*SQ];
__device__ int   g_cnt  [NE];
__device__ float g_h1   [(size_t)NE*SQ*FF];
__device__ float g_y2   [SQ*TK*HID];

// ---------------- helpers ----------------
__device__ __forceinline__ float tf32r(float x) {
    uint32_t u; asm("cvt.rna.tf32.f32 %0, %1;" : "=r"(u) : "f"(x));
    return __uint_as_float(u);
}
__device__ __forceinline__ void mma8(float* c, float a0, float a1, float a2, float a3,
                                     float b0, float b1) {
    uint32_t A0=__float_as_uint(a0), A1=__float_as_uint(a1),
             A2=__float_as_uint(a2), A3=__float_as_uint(a3),
             B0=__float_as_uint(b0), B1=__float_as_uint(b1);
    asm volatile("mma.sync.aligned.m16n8k8.row.col.f32.tf32.tf32.f32 "
        "{%0,%1,%2,%3},{%4,%5,%6,%7},{%8,%9},{%0,%1,%2,%3};\n"
        : "+f"(c[0]), "+f"(c[1]), "+f"(c[2]), "+f"(c[3])
        : "r"(A0), "r"(A1), "r"(A2), "r"(A3), "r"(B0), "r"(B1));
}
__device__ __forceinline__ uint32_t sptr(const void* p) {
    return (uint32_t)__cvta_generic_to_shared(p);
}
__device__ __forceinline__ void cp16(uint32_t s, const void* g, bool v) {
    int sz = v ? 16 : 0;
    asm volatile("cp.async.cg.shared.global [%0], [%1], 16, %2;\n"
                 :: "r"(s), "l"(g), "r"(sz));
}
#define CP_COMMIT() asm volatile("cp.async.commit_group;\n")
#define CP_WAIT1()  asm volatile("cp.async.wait_group 1;\n")

__device__ __forceinline__ float gelu_exact(float x) {
    return 0.5f * x * (1.0f + erff(x * 0.70710678118654752f));
}

// ---------------- layernorm ----------------
__global__ void ln_kernel(const float* __restrict__ x, const float* __restrict__ w,
                          const float* __restrict__ b, float* __restrict__ out) {
    int t = blockIdx.x, tid = threadIdx.x;
    float4 v = ((const float4*)(x + (size_t)t*HID))[tid];
    __shared__ float red[256];
    red[tid] = v.x+v.y+v.z+v.w; __syncthreads();
    for (int o = 128; o > 0; o >>= 1) { if (tid < o) red[tid] += red[tid+o]; __syncthreads(); }
    float mu = red[0] * (1.0f/HID); __syncthreads();
    float dx=v.x-mu, dy=v.y-mu, dz=v.z-mu, dw=v.w-mu;
    red[tid] = dx*dx+dy*dy+dz*dz+dw*dw; __syncthreads();
    for (int o = 128; o > 0; o >>= 1) { if (tid < o) red[tid] += red[tid+o]; __syncthreads(); }
    float rstd = rsqrtf(red[0] * (1.0f/HID) + 1e-5f);
    float4 wv = ((const float4*)w)[tid];
    float4 bv = ((const float4*)b)[tid];
    float4 o4;
    o4.x = dx*rstd*wv.x + bv.x; o4.y = dy*rstd*wv.y + bv.y;
    o4.z = dz*rstd*wv.z + bv.z; o4.w = dw*rstd*wv.w + bv.w;
    ((float4*)(out + (size_t)t*HID))[tid] = o4;
}

// ============ tf32 mma GEMM, 3-stage cp.async, 128x64 tiles ============
// MODE 0: QKV (NT,+bias)  MODE 1: OUT (NT,+bias+res)
// MODE 2: MOE1 (NN, gather A, gelu -> g_h1)
// MODE 3: MOE2 (NN, A=g_h1, gate*scatter -> g_y2)
#define BM 128
#define BN 64
#define BKg 16
#define NSTG 3
#define ASTR (BKg+4)   // 20
#define BSTR_NN (BN+8) // 72
#define BS_ELE 1280    // max(64*20, 16*72)

template<int MODE>
__global__ void __launch_bounds__(256,2) mma_gemm(
        const float* __restrict__ A, const float* __restrict__ Bm,
        const float* __restrict__ bias, const float* __restrict__ res,
        float* __restrict__ C, int M, int N, int Kd) {
    __shared__ float As[NSTG][BM*ASTR];
    __shared__ float Bs[NSTG][BS_ELE];
    int tid = threadIdx.x, wid = tid>>5, lid = tid&31;
    int g = lid>>2, tg = lid&3;
    int wm = (wid>>1)*32, wn = (wid&1)*32;
    int n0 = blockIdx.x*BN, m0 = blockIdx.y*BM;

    int e = 0, cnt = M;
    if (MODE >= 2) { e = blockIdx.z; cnt = g_cnt[e]; if (m0 >= cnt) return; }

    // A source row for this thread
    int arow = tid>>1;
    int ka   = (tid&1)*8;
    const float* Aptr = A;
    bool av = true;
    if (MODE <= 1) {
        Aptr = A + (size_t)(m0+arow)*Kd;
    } else if (MODE == 2) {
        int t = (m0+arow < cnt) ? g_tok[e*SQ + m0 + arow] : -1;
        av = (t >= 0);
        Aptr = A + (size_t)(av ? t : 0)*Kd;
    } else {
        int rr = m0 + arow; if (rr > SQ-1) rr = SQ-1;
        Aptr = g_h1 + (size_t)(e*SQ + rr)*Kd;
    }
    const float* Bbase = Bm;
    if (MODE >= 2) Bbase += (size_t)e * Kd * N;

    // B thread mapping
    int ntr = tid>>2, nkc = (tid&3)*4;    // NT: 64 rows x (16 k / 4)
    int bkr = tid>>4, bnc = (tid&15)*4;   // NN: 16 rows x (64 n / 4)

    auto issue = [&](int kt, int s) {
        uint32_t da = sptr(&As[s][arow*ASTR + ka]);
        const float* ga = Aptr + kt*BKg + ka;
        cp16(da,      ga,     av);
        cp16(da + 16, ga + 4, av);
        if (MODE <= 1) {
            uint32_t db = sptr(&Bs[s][ntr*ASTR + nkc]);
            const float* gb = Bbase + (size_t)(n0+ntr)*Kd + kt*BKg + nkc;
            cp16(db, gb, true);
        } else {
            uint32_t db = sptr(&Bs[s][bkr*BSTR_NN + bnc]);
            const float* gb = Bbase + (size_t)(kt*BKg+bkr)*N + n0 + bnc;
            cp16(db, gb, true);
        }
        CP_COMMIT();
    };

    float acc[2][4][4] = {};
    int KT = Kd / BKg;
    issue(0, 0);
    issue(1, 1);
    int slot = 0;
    for (int kt = 0; kt < KT; kt++) {
        CP_WAIT1();
        __syncthreads();
        {
            int nk = kt + 2;
            if (nk < KT) { int ns = slot + 2; if (ns >= NSTG) ns -= NSTG; issue(nk, ns); }
            else CP_COMMIT();
        }
        const float* as = As[slot];
        const float* bs = Bs[slot];
#pragma unroll
        for (int ks = 0; ks < 2; ks++) {
            float af[2][4], bf[4][2];
            int k0 = ks*8 + tg;
#pragma unroll
            for (int mi = 0; mi < 2; mi++) {
                int rb = wm + mi*16;
                af[mi][0] = tf32r(as[(rb+g  )*ASTR + k0]);
                af[mi][1] = tf32r(as[(rb+g+8)*ASTR + k0]);
                af[mi][2] = tf32r(as[(rb+g  )*ASTR + k0+4]);
                af[mi][3] = tf32r(as[(rb+g+8)*ASTR + k0+4]);
            }
#pragma unroll
            for (int ni = 0; ni < 4; ni++) {
                int nc = wn + ni*8 + g;
                if (MODE <= 1) {
                    bf[ni][0] = tf32r(bs[nc*ASTR + k0]);
                    bf[ni][1] = tf32r(bs[nc*ASTR + k0+4]);
                } else {
                    bf[ni][0] = tf32r(bs[(k0  )*BSTR_NN + nc]);
                    bf[ni][1] = tf32r(bs[(k0+4)*BSTR_NN + nc]);
                }
            }
#pragma unroll
            for (int mi = 0; mi < 2; mi++)
#pragma unroll
                for (int ni = 0; ni < 4; ni++)
                    mma8(acc[mi][ni], af[mi][0], af[mi][1], af[mi][2], af[mi][3],
                         bf[ni][0], bf[ni][1]);
        }
        if (++slot == NSTG) slot = 0;
    }

    // ---- epilogue ----
#pragma unroll
    for (int mi = 0; mi < 2; mi++) {
        int r1 = m0 + wm + mi*16 + g;
        int r2 = r1 + 8;
#pragma unroll
        for (int ni = 0; ni < 4; ni++) {
            int cc = n0 + wn + ni*8 + 2*tg;
            float* a = acc[mi][ni];
            if (MODE == 0 || MODE == 1) {
                float b0 = bias[cc], b1 = bias[cc+1];
                float v00 = a[0]+b0, v01 = a[1]+b1, v10 = a[2]+b0, v11 = a[3]+b1;
                if (MODE == 1) {
                    v00 += res[(size_t)r1*N + cc];   v01 += res[(size_t)r1*N + cc+1];
                    v10 += res[(size_t)r2*N + cc];   v11 += res[(size_t)r2*N + cc+1];
                }
                *(float2*)(C + (size_t)r1*N + cc) = make_float2(v00, v01);
                *(float2*)(C + (size_t)r2*N + cc) = make_float2(v10, v11);
            } else if (MODE == 2) {
                if (r1 < cnt)
                    *(float2*)(&g_h1[(size_t)(e*SQ + r1)*FF + cc]) =
                        make_float2(gelu_exact(a[0]), gelu_exact(a[1]));
                if (r2 < cnt)
                    *(float2*)(&g_h1[(size_t)(e*SQ + r2)*FF + cc]) =
                        make_float2(gelu_exact(a[2]), gelu_exact(a[3]));
            } else {
                if (r1 < cnt) {
                    int t = g_tok[e*SQ+r1], sl = g_slot[e*SQ+r1];
                    float gt = g_gate[e*SQ+r1];
                    *(float2*)(&g_y2[((size_t)t*TK+sl)*HID + cc]) =
                        make_float2(gt*a[0], gt*a[1]);
                }
                if (r2 < cnt) {
                    int t = g_tok[e*SQ+r2], sl = g_slot[e*SQ+r2];
                    float gt = g_gate[e*SQ+r2];
                    *(float2*)(&g_y2[((size_t)t*TK+sl)*HID + cc]) =
                        make_float2(gt*a[2], gt*a[3]);
                }
            }
        }
    }
}

// ================= flash attention (tf32 mma, online softmax) =================
#define FBM 128
__global__ void __launch_bounds__(256) flash_kernel(const float* __restrict__ qkv,
                                                    float* __restrict__ attn) {
    int h = blockIdx.y;
    int q0 = blockIdx.x * FBM;
    int tid = threadIdx.x, wid = tid>>5, lid = tid&31;
    int wm = wid*16;
    int g = lid>>2, tg = lid&3;
    __shared__ float Kv[64*68];
    __shared__ float Vs[64*72];

    float qf[8][4];
    {
        const float* Q = qkv + (size_t)(q0+wm)*H3 + h*HD;
#pragma unroll
        for (int kc = 0; kc < 8; kc++) {
            int c = kc*8 + tg;
            qf[kc][0] = tf32r(Q[(size_t)g*H3     + c    ] * 0.125f);
            qf[kc][1] = tf32r(Q[(size_t)(g+8)*H3 + c    ] * 0.125f);
            qf[kc][2] = tf32r(Q[(size_t)g*H3     + c + 4] * 0.125f);
            qf[kc][3] = tf32r(Q[(size_t)(g+8)*H3 + c + 4] * 0.125f);
        }
    }

    float Oc[8][4] = {};
    float m1 = -1e30f, m2 = -1e30f, l1 = 0.f, l2 = 0.f;
    int r1 = q0 + wm + g, r2 = r1 + 8;

    for (int j0 = 0; j0 < q0 + FBM; j0 += 64) {
        __syncthreads();
        {
            int r = tid & 63;
            int cb = (tid >> 6) * 16;
            const float* K = qkv + (size_t)(j0+r)*H3 + HID   + h*HD;
            const float* V = qkv + (size_t)(j0+r)*H3 + 2*HID + h*HD;
#pragma unroll
            for (int i = 0; i < 4; i++) {
                int c = cb + i*4;
                *(float4*)(&Kv[r*68 + c]) = *(const float4*)(K + c);
                *(float4*)(&Vs[r*72 + c]) = *(const float4*)(V + c);
            }
        }
        __syncthreads();

        float Sc[8][4];
#pragma unroll
        for (int j = 0; j < 8; j++) {
            Sc[j][0] = Sc[j][1] = Sc[j][2] = Sc[j][3] = 0.f;
#pragma unroll
            for (int kc = 0; kc < 8; kc++) {
                float b0 = tf32r(Kv[(j*8+g)*68 + kc*8+tg]);
                float b1 = tf32r(Kv[(j*8+g)*68 + kc*8+tg+4]);
                mma8(Sc[j], qf[kc][0], qf[kc][1], qf[kc][2], qf[kc][3], b0, b1);
            }
        }
        if (j0 + 63 > q0 + wm) {
#pragma unroll
            for (int j = 0; j < 8; j++) {
                int cb = j0 + j*8 + 2*tg;
                if (cb   > r1) Sc[j][0] = -1e30f;
                if (cb+1 > r1) Sc[j][1] = -1e30f;
                if (cb   > r2) Sc[j][2] = -1e30f;
                if (cb+1 > r2) Sc[j][3] = -1e30f;
            }
        }
        float mx1 = -1e30f, mx2 = -1e30f;
#pragma unroll
        for (int j = 0; j < 8; j++) {
            mx1 = fmaxf(mx1, fmaxf(Sc[j][0], Sc[j][1]));
            mx2 = fmaxf(mx2, fmaxf(Sc[j][2], Sc[j][3]));
        }
        mx1 = fmaxf(mx1, __shfl_xor_sync(0xffffffffu, mx1, 1));
        mx1 = fmaxf(mx1, __shfl_xor_sync(0xffffffffu, mx1, 2));
        mx2 = fmaxf(mx2, __shfl_xor_sync(0xffffffffu, mx2, 1));
        mx2 = fmaxf(mx2, __shfl_xor_sync(0xffffffffu, mx2, 2));
        float nm1 = fmaxf(m1, mx1), nm2 = fmaxf(m2, mx2);
        float al1 = __expf(m1 - nm1), al2 = __expf(m2 - nm2);
        float s1 = 0.f, s2 = 0.f;
#pragma unroll
        for (int j = 0; j < 8; j++) {
            Sc[j][0] = __expf(Sc[j][0] - nm1);
            Sc[j][1] = __expf(Sc[j][1] - nm1);
            Sc[j][2] = __expf(Sc[j][2] - nm2);
            Sc[j][3] = __expf(Sc[j][3] - nm2);
            s1 += Sc[j][0] + Sc[j][1];
            s2 += Sc[j][2] + Sc[j][3];
        }
        s1 += __shfl_xor_sync(0xffffffffu, s1, 1);
        s1 += __shfl_xor_sync(0xffffffffu, s1, 2);
        s2 += __shfl_xor_sync(0xffffffffu, s2, 1);
        s2 += __shfl_xor_sync(0xffffffffu, s2, 2);
        l1 = l1*al1 + s1; l2 = l2*al2 + s2;
        m1 = nm1; m2 = nm2;
#pragma unroll
        for (int jd = 0; jd < 8; jd++) {
            Oc[jd][0] *= al1; Oc[jd][1] *= al1;
            Oc[jd][2] *= al2; Oc[jd][3] *= al2;
        }
#pragma unroll
        for (int j = 0; j < 8; j++) {
            Sc[j][0] = tf32r(Sc[j][0]); Sc[j][1] = tf32r(Sc[j][1]);
            Sc[j][2] = tf32r(Sc[j][2]); Sc[j][3] = tf32r(Sc[j][3]);
        }
        int lane0 = (g<<2) + (tg>>1);
        int sel = tg & 1;
#pragma unroll
        for (int kc = 0; kc < 8; kc++) {
            float u0 = __shfl_sync(0xffffffffu, Sc[kc][0], lane0);
            float u1 = __shfl_sync(0xffffffffu, Sc[kc][1], lane0);
            float a0 = sel ? u1 : u0;
            float u2 = __shfl_sync(0xffffffffu, Sc[kc][2], lane0);
            float u3 = __shfl_sync(0xffffffffu, Sc[kc][3], lane0);
            float a1 = sel ? u3 : u2;
            float u4 = __shfl_sync(0xffffffffu, Sc[kc][0], lane0+2);
            float u5 = __shfl_sync(0xffffffffu, Sc[kc][1], lane0+2);
            float a2 = sel ? u5 : u4;
            float u6 = __shfl_sync(0xffffffffu, Sc[kc][2], lane0+2);
            float u7 = __shfl_sync(0xffffffffu, Sc[kc][3], lane0+2);
            float a3 = sel ? u7 : u6;
#pragma unroll
            for (int jd = 0; jd < 8; jd++) {
                float b0 = tf32r(Vs[(kc*8+tg  )*72 + jd*8+g]);
                float b1 = tf32r(Vs[(kc*8+tg+4)*72 + jd*8+g]);
                mma8(Oc[jd], a0, a1, a2, a3, b0, b1);
            }
        }
    }

    float inv1 = 1.f / l1, inv2 = 1.f / l2;
#pragma unroll
    for (int jd = 0; jd < 8; jd++) {
        int c = h*HD + jd*8 + 2*tg;
        *(float2*)(attn + (size_t)r1*HID + c) = make_float2(Oc[jd][0]*inv1, Oc[jd][1]*inv1);
        *(float2*)(attn + (size_t)r2*HID + c) = make_float2(Oc[jd][2]*inv2, Oc[jd][3]*inv2);
    }
}

// ---------------- router ----------------
__global__ void router_kernel(const float* __restrict__ hn2, const float* __restrict__ rw) {
    int t = blockIdx.x, tid = threadIdx.x;
    __shared__ float part[NE][256];
    float loc[NE] = {};
    for (int hh = tid; hh < HID; hh += 256) {
        float xv = hn2[(size_t)t*HID + hh];
#pragma unroll
        for (int e = 0; e < NE; e++) loc[e] += xv * rw[e*HID + hh];
    }
#pragma unroll
    for (int e = 0; e < NE; e++) part[e][tid] = loc[e];
    __syncthreads();
    for (int o = 128; o > 0; o >>= 1) {
        if (tid < o)
#pragma unroll
            for (int e = 0; e < NE; e++) part[e][tid] += part[e][tid+o];
        __syncthreads();
    }
    if (tid == 0) {
        float lg[NE], mx = -1e30f;
#pragma unroll
        for (int e = 0; e < NE; e++) { lg[e] = part[e][0]; mx = fmaxf(mx, lg[e]); }
        float s = 0.f;
#pragma unroll
        for (int e = 0; e < NE; e++) { lg[e] = expf(lg[e]-mx); s += lg[e]; }
        float inv = 1.0f/s;
#pragma unroll
        for (int e = 0; e < NE; e++) lg[e] *= inv;
        int i0 = 0; float v0 = lg[0];
#pragma unroll
        for (int e = 1; e < NE; e++) if (lg[e] > v0) { v0 = lg[e]; i0 = e; }
        int i1 = -1; float v1 = -1e30f;
#pragma unroll
        for (int e = 0; e < NE; e++) if (e != i0 && lg[e] > v1) { v1 = lg[e]; i1 = e; }
        g_topi[t*TK+0] = i0; g_topw[t*TK+0] = v0;
        g_topi[t*TK+1] = i1; g_topw[t*TK+1] = v1;
    }
}

// ---------------- deterministic expert lists ----------------
__global__ void build_lists_kernel() {
    int e = blockIdx.x, tid = threadIdx.x;
    const int CH = SQ / 256;
    int ids[CH], slots[CH]; float gs[CH];
    int loc = 0;
    for (int c = 0; c < CH; c++) {
        int t = tid*CH + c;
        if (g_topi[t*TK+0] == e)      { ids[loc]=t; slots[loc]=0; gs[loc]=g_topw[t*TK+0]; loc++; }
        else if (g_topi[t*TK+1] == e) { ids[loc]=t; slots[loc]=1; gs[loc]=g_topw[t*TK+1]; loc++; }
    }
    __shared__ int sc[256];
    sc[tid] = loc; __syncthreads();
    for (int o = 1; o < 256; o <<= 1) {
        int v = (tid >= o) ? sc[tid-o] : 0;
        __syncthreads();
        sc[tid] += v;
        __syncthreads();
    }
    int off = sc[tid] - loc;
    for (int c = 0; c < loc; c++) {
        g_tok [e*SQ + off + c] = ids[c];
        g_slot[e*SQ + off + c] = slots[c];
        g_gate[e*SQ + off + c] = gs[c];
    }
    if (tid == 255) g_cnt[e] = sc[255];
}

// ---------------- out = x1 + y2[:,0] + y2[:,1] ----------------
__global__ void final_kernel(float* __restrict__ out) {
    int idx = blockIdx.x * 256 + threadIdx.x;
    int t = idx / HID, hh = idx % HID;
    out[idx] = g_x1[idx] + g_y2[((size_t)t*TK)*HID + hh] + g_y2[((size_t)t*TK + 1)*HID + hh];
}

// ---------------- launch ----------------
extern "C" void kernel_launch(void* const* d_in, const int* in_sizes, int n_in,
                              void* d_out, int out_size) {
    (void)in_sizes; (void)n_in; (void)out_size;
    const float* x          = (const float*)d_in[0];
    const float* ln1_w      = (const float*)d_in[1];
    const float* ln1_b      = (const float*)d_in[2];
    const float* in_proj_w  = (const float*)d_in[3];
    const float* in_proj_b  = (const float*)d_in[4];
    const float* out_proj_w = (const float*)d_in[5];
    const float* out_proj_b = (const float*)d_in[6];
    const float* ln2_w      = (const float*)d_in[7];
    const float* ln2_b      = (const float*)d_in[8];
    const float* router_w   = (const float*)d_in[9];
    const float* w1         = (const float*)d_in[10];
    const float* w2         = (const float*)d_in[11];
    float* out = (float*)d_out;

    float *hn, *qkv, *attn, *x1, *hn2;
    cudaGetSymbolAddress((void**)&hn,   g_hn);
    cudaGetSymbolAddress((void**)&qkv,  g_qkv);
    cudaGetSymbolAddress((void**)&attn, g_attn);
    cudaGetSymbolAddress((void**)&x1,   g_x1);
    cudaGetSymbolAddress((void**)&hn2,  g_hn2);

    ln_kernel<<<SQ, 256>>>(x, ln1_w, ln1_b, hn);
    mma_gemm<0><<<dim3(H3/BN, SQ/BM), 256>>>(hn, in_proj_w, in_proj_b, nullptr, qkv, SQ, H3, HID);
    flash_kernel<<<dim3(SQ/FBM, NH), 256>>>(qkv, attn);
    mma_gemm<1><<<dim3(HID/BN, SQ/BM), 256>>>(attn, out_proj_w, out_proj_b, x, x1, SQ, HID, HID);
    ln_kernel<<<SQ, 256>>>(x1, ln2_w, ln2_b, hn2);
    router_kernel<<<SQ, 256>>>(hn2, router_w);
    build_lists_kernel<<<NE, 256>>>();
    mma_gemm<2><<<dim3(FF/BN, SQ/BM, NE), 256>>>(hn2, w1, nullptr, nullptr, nullptr, SQ, FF, HID);
    mma_gemm<3><<<dim3(HID/BN, SQ/BM, NE), 256>>>(nullptr, w2, nullptr, nullptr, nullptr, SQ, HID, FF);
    final_kernel<<<(SQ*HID)/256, 256>>>(out);
}

// round 9
// speedup vs baseline: 1.1602x; 1.1602x over previous
#include <cuda_runtime.h>
#include <math.h>
#include <stdint.h>

#define SQ   2048
#define HID  1024
#define NH   16
#define HD   64
#define H3   3072
#define NE   8
#define TK   2
#define FF   2048

// ---------------- scratch ----------------
__device__ float g_hn   [SQ*HID];
__device__ float g_qkv  [SQ*H3];
__device__ float g_attn [SQ*HID];
__device__ float g_x1   [SQ*HID];
__device__ float g_hn2  [SQ*HID];   // tf32-rounded (MoE GEMM A)
__device__ float g_hn2f [SQ*HID];   // full precision (router)
__device__ int   g_topi [SQ*TK];
__device__ float g_topw [SQ*TK];
__device__ int   g_tok  [NE*SQ];
__device__ float g_gate [NE*SQ];
__device__ int   g_slot [NE*SQ];
__device__ int   g_cnt  [NE];
__device__ float g_h1   [(size_t)NE*SQ*FF];
__device__ float g_y2   [SQ*TK*HID];

// ---------------- helpers ----------------
__device__ __forceinline__ float tf32r(float x) {
    uint32_t u; asm("cvt.rna.tf32.f32 %0, %1;" : "=r"(u) : "f"(x));
    return __uint_as_float(u);
}
__device__ __forceinline__ void mma8(float* c, float a0, float a1, float a2, float a3,
                                     float b0, float b1) {
    uint32_t A0=__float_as_uint(a0), A1=__float_as_uint(a1),
             A2=__float_as_uint(a2), A3=__float_as_uint(a3),
             B0=__float_as_uint(b0), B1=__float_as_uint(b1);
    asm volatile("mma.sync.aligned.m16n8k8.row.col.f32.tf32.tf32.f32 "
        "{%0,%1,%2,%3},{%4,%5,%6,%7},{%8,%9},{%0,%1,%2,%3};\n"
        : "+f"(c[0]), "+f"(c[1]), "+f"(c[2]), "+f"(c[3])
        : "r"(A0), "r"(A1), "r"(A2), "r"(A3), "r"(B0), "r"(B1));
}
__device__ __forceinline__ uint32_t sptr(const void* p) {
    return (uint32_t)__cvta_generic_to_shared(p);
}
__device__ __forceinline__ void cp16(uint32_t s, const void* g, bool v) {
    int sz = v ? 16 : 0;
    asm volatile("cp.async.cg.shared.global [%0], [%1], 16, %2;\n"
                 :: "r"(s), "l"(g), "r"(sz));
}
#define CP_COMMIT() asm volatile("cp.async.commit_group;\n")
#define CP_WAIT1()  asm volatile("cp.async.wait_group 1;\n")

__device__ __forceinline__ float gelu_exact(float x) {
    return 0.5f * x * (1.0f + erff(x * 0.70710678118654752f));
}

// ---------------- layernorm: rounded output + optional full-precision copy ----
__global__ void ln_kernel(const float* __restrict__ x, const float* __restrict__ w,
                          const float* __restrict__ b, float* __restrict__ out,
                          float* __restrict__ out_full) {
    int t = blockIdx.x, tid = threadIdx.x;
    float4 v = ((const float4*)(x + (size_t)t*HID))[tid];
    __shared__ float red[256];
    red[tid] = v.x+v.y+v.z+v.w; __syncthreads();
    for (int o = 128; o > 0; o >>= 1) { if (tid < o) red[tid] += red[tid+o]; __syncthreads(); }
    float mu = red[0] * (1.0f/HID); __syncthreads();
    float dx=v.x-mu, dy=v.y-mu, dz=v.z-mu, dw=v.w-mu;
    red[tid] = dx*dx+dy*dy+dz*dz+dw*dw; __syncthreads();
    for (int o = 128; o > 0; o >>= 1) { if (tid < o) red[tid] += red[tid+o]; __syncthreads(); }
    float rstd = rsqrtf(red[0] * (1.0f/HID) + 1e-5f);
    float4 wv = ((const float4*)w)[tid];
    float4 bv = ((const float4*)b)[tid];
    float fx = dx*rstd*wv.x + bv.x, fy = dy*rstd*wv.y + bv.y;
    float fz = dz*rstd*wv.z + bv.z, fw = dw*rstd*wv.w + bv.w;
    if (out_full) {
        float4 f4; f4.x=fx; f4.y=fy; f4.z=fz; f4.w=fw;
        ((float4*)(out_full + (size_t)t*HID))[tid] = f4;
    }
    float4 o4;
    o4.x = tf32r(fx); o4.y = tf32r(fy); o4.z = tf32r(fz); o4.w = tf32r(fw);
    ((float4*)(out + (size_t)t*HID))[tid] = o4;
}

// ===== tf32 mma GEMM: 128x128 block, 64x32 warp tile, 3-stage cp.async =====
// A operands pre-rounded to tf32 at producers; only B gets cvt in-loop.
#define BM 128
#define BN 128
#define BKg 16
#define NSTG 3
#define ASTR (BKg+4)   // 20
#define BSTR_NN (BN+8) // 136
#define STG_F  5120
#define GSMEM  (NSTG*STG_F*4)

template<int MODE>
__global__ void __launch_bounds__(256,2) mma_gemm(
        const float* __restrict__ A, const float* __restrict__ Bm,
        const float* __restrict__ bias, const float* __restrict__ res,
        float* __restrict__ C, int M, int N, int Kd) {
    extern __shared__ float sm[];
    int tid = threadIdx.x, wid = tid>>5, lid = tid&31;
    int g = lid>>2, tg = lid&3;
    int wm = (wid>>2)*64, wn = (wid&3)*32;
    int n0 = blockIdx.x*BN, m0 = blockIdx.y*BM;

    int e = 0, cnt = M;
    if (MODE >= 2) { e = blockIdx.z; cnt = g_cnt[e]; if (m0 >= cnt) return; }

    int arow = tid>>1;
    int ka   = (tid&1)*8;
    const float* Aptr = A;
    bool av = true;
    if (MODE <= 1) {
        Aptr = A + (size_t)(m0+arow)*Kd;
    } else if (MODE == 2) {
        int t = (m0+arow < cnt) ? g_tok[e*SQ + m0 + arow] : -1;
        av = (t >= 0);
        Aptr = A + (size_t)(av ? t : 0)*Kd;
    } else {
        int rr = m0 + arow; if (rr > SQ-1) rr = SQ-1;
        Aptr = g_h1 + (size_t)(e*SQ + rr)*Kd;
    }
    const float* Bbase = Bm;
    if (MODE >= 2) Bbase += (size_t)e * Kd * N;

    int bkr = tid>>4, bnc = (tid&15)*4;

    auto issue = [&](int kt, int s) {
        float* As = sm + s*STG_F;
        float* Bs = As + 2560;
        uint32_t da = sptr(&As[arow*ASTR + ka]);
        const float* ga = Aptr + kt*BKg + ka;
        cp16(da,      ga,     av);
        cp16(da + 16, ga + 4, av);
        if (MODE <= 1) {
            uint32_t db = sptr(&Bs[arow*ASTR + ka]);
            const float* gb = Bbase + (size_t)(n0+arow)*Kd + kt*BKg + ka;
            cp16(db,      gb,     true);
            cp16(db + 16, gb + 4, true);
        } else {
            uint32_t db = sptr(&Bs[bkr*BSTR_NN + bnc]);
            const float* gb = Bbase + (size_t)(kt*BKg+bkr)*N + n0 + bnc;
            cp16(db,       gb,      true);
            cp16(db + 256, gb + 64, true);
        }
        CP_COMMIT();
    };

    float acc[4][4][4] = {};
    int KT = Kd / BKg;
    issue(0, 0);
    issue(1, 1);
    int slot = 0;
    for (int kt = 0; kt < KT; kt++) {
        CP_WAIT1();
        __syncthreads();
        {
            int nk = kt + 2;
            if (nk < KT) { int ns = slot + 2; if (ns >= NSTG) ns -= NSTG; issue(nk, ns); }
            else CP_COMMIT();
        }
        const float* as = sm + slot*STG_F;
        const float* bs = as + 2560;
#pragma unroll
        for (int ks = 0; ks < 2; ks++) {
            float af[4][4], bf[4][2];
            int k0 = ks*8 + tg;
#pragma unroll
            for (int mi = 0; mi < 4; mi++) {
                int rb = wm + mi*16;
                af[mi][0] = as[(rb+g  )*ASTR + k0];
                af[mi][1] = as[(rb+g+8)*ASTR + k0];
                af[mi][2] = as[(rb+g  )*ASTR + k0+4];
                af[mi][3] = as[(rb+g+8)*ASTR + k0+4];
            }
#pragma unroll
            for (int ni = 0; ni < 4; ni++) {
                int nc = wn + ni*8 + g;
                if (MODE <= 1) {
                    bf[ni][0] = tf32r(bs[nc*ASTR + k0]);
                    bf[ni][1] = tf32r(bs[nc*ASTR + k0+4]);
                } else {
                    bf[ni][0] = tf32r(bs[(k0  )*BSTR_NN + nc]);
                    bf[ni][1] = tf32r(bs[(k0+4)*BSTR_NN + nc]);
                }
            }
#pragma unroll
            for (int mi = 0; mi < 4; mi++)
#pragma unroll
                for (int ni = 0; ni < 4; ni++)
                    mma8(acc[mi][ni], af[mi][0], af[mi][1], af[mi][2], af[mi][3],
                         bf[ni][0], bf[ni][1]);
        }
        if (++slot == NSTG) slot = 0;
    }

    // ---- epilogue ----
#pragma unroll
    for (int mi = 0; mi < 4; mi++) {
        int r1 = m0 + wm + mi*16 + g;
        int r2 = r1 + 8;
#pragma unroll
        for (int ni = 0; ni < 4; ni++) {
            int cc = n0 + wn + ni*8 + 2*tg;
            float* a = acc[mi][ni];
            if (MODE == 0 || MODE == 1) {
                float b0 = bias[cc], b1 = bias[cc+1];
                float v00 = a[0]+b0, v01 = a[1]+b1, v10 = a[2]+b0, v11 = a[3]+b1;
                if (MODE == 1) {
                    v00 += res[(size_t)r1*N + cc];   v01 += res[(size_t)r1*N + cc+1];
                    v10 += res[(size_t)r2*N + cc];   v11 += res[(size_t)r2*N + cc+1];
                }
                *(float2*)(C + (size_t)r1*N + cc) = make_float2(v00, v01);
                *(float2*)(C + (size_t)r2*N + cc) = make_float2(v10, v11);
            } else if (MODE == 2) {
                if (r1 < cnt)
                    *(float2*)(&g_h1[(size_t)(e*SQ + r1)*FF + cc]) =
                        make_float2(tf32r(gelu_exact(a[0])), tf32r(gelu_exact(a[1])));
                if (r2 < cnt)
                    *(float2*)(&g_h1[(size_t)(e*SQ + r2)*FF + cc]) =
                        make_float2(tf32r(gelu_exact(a[2])), tf32r(gelu_exact(a[3])));
            } else {
                if (r1 < cnt) {
                    int t = g_tok[e*SQ+r1], sl = g_slot[e*SQ+r1];
                    float gt = g_gate[e*SQ+r1];
                    *(float2*)(&g_y2[((size_t)t*TK+sl)*HID + cc]) =
                        make_float2(gt*a[0], gt*a[1]);
                }
                if (r2 < cnt) {
                    int t = g_tok[e*SQ+r2], sl = g_slot[e*SQ+r2];
                    float gt = g_gate[e*SQ+r2];
                    *(float2*)(&g_y2[((size_t)t*TK+sl)*HID + cc]) =
                        make_float2(gt*a[2], gt*a[3]);
                }
            }
        }
    }
}

// ================= flash attention (tf32 mma, online softmax) =================
#define FBM 128
__global__ void __launch_bounds__(256) flash_kernel(const float* __restrict__ qkv,
                                                    float* __restrict__ attn) {
    int h = blockIdx.y;
    int q0 = blockIdx.x * FBM;
    int tid = threadIdx.x, wid = tid>>5, lid = tid&31;
    int wm = wid*16;
    int g = lid>>2, tg = lid&3;
    __shared__ float Kv[64*68];
    __shared__ float Vs[64*72];

    float qf[8][4];
    {
        const float* Q = qkv + (size_t)(q0+wm)*H3 + h*HD;
#pragma unroll
        for (int kc = 0; kc < 8; kc++) {
            int c = kc*8 + tg;
            qf[kc][0] = tf32r(Q[(size_t)g*H3     + c    ] * 0.125f);
            qf[kc][1] = tf32r(Q[(size_t)(g+8)*H3 + c    ] * 0.125f);
            qf[kc][2] = tf32r(Q[(size_t)g*H3     + c + 4] * 0.125f);
            qf[kc][3] = tf32r(Q[(size_t)(g+8)*H3 + c + 4] * 0.125f);
        }
    }

    float Oc[8][4] = {};
    float m1 = -1e30f, m2 = -1e30f, l1 = 0.f, l2 = 0.f;
    int r1 = q0 + wm + g, r2 = r1 + 8;

    for (int j0 = 0; j0 < q0 + FBM; j0 += 64) {
        __syncthreads();
        {
            int r = tid & 63;
            int cb = (tid >> 6) * 16;
            const float* K = qkv + (size_t)(j0+r)*H3 + HID   + h*HD;
            const float* V = qkv + (size_t)(j0+r)*H3 + 2*HID + h*HD;
#pragma unroll
            for (int i = 0; i < 4; i++) {
                int c = cb + i*4;
                *(float4*)(&Kv[r*68 + c]) = *(const float4*)(K + c);
                *(float4*)(&Vs[r*72 + c]) = *(const float4*)(V + c);
            }
        }
        __syncthreads();

        float Sc[8][4];
#pragma unroll
        for (int j = 0; j < 8; j++) {
            Sc[j][0] = Sc[j][1] = Sc[j][2] = Sc[j][3] = 0.f;
#pragma unroll
            for (int kc = 0; kc < 8; kc++) {
                float b0 = tf32r(Kv[(j*8+g)*68 + kc*8+tg]);
                float b1 = tf32r(Kv[(j*8+g)*68 + kc*8+tg+4]);
                mma8(Sc[j], qf[kc][0], qf[kc][1], qf[kc][2], qf[kc][3], b0, b1);
            }
        }
        if (j0 + 63 > q0 + wm) {
#pragma unroll
            for (int j = 0; j < 8; j++) {
                int cb = j0 + j*8 + 2*tg;
                if (cb   > r1) Sc[j][0] = -1e30f;
                if (cb+1 > r1) Sc[j][1] = -1e30f;
                if (cb   > r2) Sc[j][2] = -1e30f;
                if (cb+1 > r2) Sc[j][3] = -1e30f;
            }
        }
        float mx1 = -1e30f, mx2 = -1e30f;
#pragma unroll
        for (int j = 0; j < 8; j++) {
            mx1 = fmaxf(mx1, fmaxf(Sc[j][0], Sc[j][1]));
            mx2 = fmaxf(mx2, fmaxf(Sc[j][2], Sc[j][3]));
        }
        mx1 = fmaxf(mx1, __shfl_xor_sync(0xffffffffu, mx1, 1));
        mx1 = fmaxf(mx1, __shfl_xor_sync(0xffffffffu, mx1, 2));
        mx2 = fmaxf(mx2, __shfl_xor_sync(0xffffffffu, mx2, 1));
        mx2 = fmaxf(mx2, __shfl_xor_sync(0xffffffffu, mx2, 2));
        float nm1 = fmaxf(m1, mx1), nm2 = fmaxf(m2, mx2);
        float al1 = __expf(m1 - nm1), al2 = __expf(m2 - nm2);
        float s1 = 0.f, s2 = 0.f;
#pragma unroll
        for (int j = 0; j < 8; j++) {
            Sc[j][0] = __expf(Sc[j][0] - nm1);
            Sc[j][1] = __expf(Sc[j][1] - nm1);
            Sc[j][2] = __expf(Sc[j][2] - nm2);
            Sc[j][3] = __expf(Sc[j][3] - nm2);
            s1 += Sc[j][0] + Sc[j][1];
            s2 += Sc[j][2] + Sc[j][3];
        }
        s1 += __shfl_xor_sync(0xffffffffu, s1, 1);
        s1 += __shfl_xor_sync(0xffffffffu, s1, 2);
        s2 += __shfl_xor_sync(0xffffffffu, s2, 1);
        s2 += __shfl_xor_sync(0xffffffffu, s2, 2);
        l1 = l1*al1 + s1; l2 = l2*al2 + s2;
        m1 = nm1; m2 = nm2;
#pragma unroll
        for (int jd = 0; jd < 8; jd++) {
            Oc[jd][0] *= al1; Oc[jd][1] *= al1;
            Oc[jd][2] *= al2; Oc[jd][3] *= al2;
        }
#pragma unroll
        for (int j = 0; j < 8; j++) {
            Sc[j][0] = tf32r(Sc[j][0]); Sc[j][1] = tf32r(Sc[j][1]);
            Sc[j][2] = tf32r(Sc[j][2]); Sc[j][3] = tf32r(Sc[j][3]);
        }
        int lane0 = (g<<2) + (tg>>1);
        int sel = tg & 1;
#pragma unroll
        for (int kc = 0; kc < 8; kc++) {
            float u0 = __shfl_sync(0xffffffffu, Sc[kc][0], lane0);
            float u1 = __shfl_sync(0xffffffffu, Sc[kc][1], lane0);
            float a0 = sel ? u1 : u0;
            float u2 = __shfl_sync(0xffffffffu, Sc[kc][2], lane0);
            float u3 = __shfl_sync(0xffffffffu, Sc[kc][3], lane0);
            float a1 = sel ? u3 : u2;
            float u4 = __shfl_sync(0xffffffffu, Sc[kc][0], lane0+2);
            float u5 = __shfl_sync(0xffffffffu, Sc[kc][1], lane0+2);
            float a2 = sel ? u5 : u4;
            float u6 = __shfl_sync(0xffffffffu, Sc[kc][2], lane0+2);
            float u7 = __shfl_sync(0xffffffffu, Sc[kc][3], lane0+2);
            float a3 = sel ? u7 : u6;
#pragma unroll
            for (int jd = 0; jd < 8; jd++) {
                float b0 = tf32r(Vs[(kc*8+tg  )*72 + jd*8+g]);
                float b1 = tf32r(Vs[(kc*8+tg+4)*72 + jd*8+g]);
                mma8(Oc[jd], a0, a1, a2, a3, b0, b1);
            }
        }
    }

    float inv1 = 1.f / l1, inv2 = 1.f / l2;
#pragma unroll
    for (int jd = 0; jd < 8; jd++) {
        int c = h*HD + jd*8 + 2*tg;
        *(float2*)(attn + (size_t)r1*HID + c) =
            make_float2(tf32r(Oc[jd][0]*inv1), tf32r(Oc[jd][1]*inv1));
        *(float2*)(attn + (size_t)r2*HID + c) =
            make_float2(tf32r(Oc[jd][2]*inv2), tf32r(Oc[jd][3]*inv2));
    }
}

// ---------------- router (full-precision hn2) ----------------
__global__ void router_kernel(const float* __restrict__ hn2, const float* __restrict__ rw) {
    int t = blockIdx.x, tid = threadIdx.x;
    __shared__ float part[NE][256];
    float loc[NE] = {};
    for (int hh = tid; hh < HID; hh += 256) {
        float xv = hn2[(size_t)t*HID + hh];
#pragma unroll
        for (int e = 0; e < NE; e++) loc[e] += xv * rw[e*HID + hh];
    }
#pragma unroll
    for (int e = 0; e < NE; e++) part[e][tid] = loc[e];
    __syncthreads();
    for (int o = 128; o > 0; o >>= 1) {
        if (tid < o)
#pragma unroll
            for (int e = 0; e < NE; e++) part[e][tid] += part[e][tid+o];
        __syncthreads();
    }
    if (tid == 0) {
        float lg[NE], mx = -1e30f;
#pragma unroll
        for (int e = 0; e < NE; e++) { lg[e] = part[e][0]; mx = fmaxf(mx, lg[e]); }
        float s = 0.f;
#pragma unroll
        for (int e = 0; e < NE; e++) { lg[e] = expf(lg[e]-mx); s += lg[e]; }
        float inv = 1.0f/s;
#pragma unroll
        for (int e = 0; e < NE; e++) lg[e] *= inv;
        int i0 = 0; float v0 = lg[0];
#pragma unroll
        for (int e = 1; e < NE; e++) if (lg[e] > v0) { v0 = lg[e]; i0 = e; }
        int i1 = -1; float v1 = -1e30f;
#pragma unroll
        for (int e = 0; e < NE; e++) if (e != i0 && lg[e] > v1) { v1 = lg[e]; i1 = e; }
        g_topi[t*TK+0] = i0; g_topw[t*TK+0] = v0;
        g_topi[t*TK+1] = i1; g_topw[t*TK+1] = v1;
    }
}

// ---------------- deterministic expert lists ----------------
__global__ void build_lists_kernel() {
    int e = blockIdx.x, tid = threadIdx.x;
    const int CH = SQ / 256;
    int ids[CH], slots[CH]; float gs[CH];
    int loc = 0;
    for (int c = 0; c < CH; c++) {
        int t = tid*CH + c;
        if (g_topi[t*TK+0] == e)      { ids[loc]=t; slots[loc]=0; gs[loc]=g_topw[t*TK+0]; loc++; }
        else if (g_topi[t*TK+1] == e) { ids[loc]=t; slots[loc]=1; gs[loc]=g_topw[t*TK+1]; loc++; }
    }
    __shared__ int sc[256];
    sc[tid] = loc; __syncthreads();
    for (int o = 1; o < 256; o <<= 1) {
        int v = (tid >= o) ? sc[tid-o] : 0;
        __syncthreads();
        sc[tid] += v;
        __syncthreads();
    }
    int off = sc[tid] - loc;
    for (int c = 0; c < loc; c++) {
        g_tok [e*SQ + off + c] = ids[c];
        g_slot[e*SQ + off + c] = slots[c];
        g_gate[e*SQ + off + c] = gs[c];
    }
    if (tid == 255) g_cnt[e] = sc[255];
}

// ---------------- out = x1 + y2[:,0] + y2[:,1] ----------------
__global__ void final_kernel(float* __restrict__ out) {
    int idx = blockIdx.x * 256 + threadIdx.x;
    int t = idx / HID, hh = idx % HID;
    out[idx] = g_x1[idx] + g_y2[((size_t)t*TK)*HID + hh] + g_y2[((size_t)t*TK + 1)*HID + hh];
}

// ---------------- launch ----------------
extern "C" void kernel_launch(void* const* d_in, const int* in_sizes, int n_in,
                              void* d_out, int out_size) {
    (void)in_sizes; (void)n_in; (void)out_size;
    const float* x          = (const float*)d_in[0];
    const float* ln1_w      = (const float*)d_in[1];
    const float* ln1_b      = (const float*)d_in[2];
    const float* in_proj_w  = (const float*)d_in[3];
    const float* in_proj_b  = (const float*)d_in[4];
    const float* out_proj_w = (const float*)d_in[5];
    const float* out_proj_b = (const float*)d_in[6];
    const float* ln2_w      = (const float*)d_in[7];
    const float* ln2_b      = (const float*)d_in[8];
    const float* router_w   = (const float*)d_in[9];
    const float* w1         = (const float*)d_in[10];
    const float* w2         = (const float*)d_in[11];
    float* out = (float*)d_out;

    float *hn, *qkv, *attn, *x1, *hn2, *hn2f;
    cudaGetSymbolAddress((void**)&hn,   g_hn);
    cudaGetSymbolAddress((void**)&qkv,  g_qkv);
    cudaGetSymbolAddress((void**)&attn, g_attn);
    cudaGetSymbolAddress((void**)&x1,   g_x1);
    cudaGetSymbolAddress((void**)&hn2,  g_hn2);
    cudaGetSymbolAddress((void**)&hn2f, g_hn2f);

    cudaFuncSetAttribute(mma_gemm<0>, cudaFuncAttributeMaxDynamicSharedMemorySize, GSMEM);
    cudaFuncSetAttribute(mma_gemm<1>, cudaFuncAttributeMaxDynamicSharedMemorySize, GSMEM);
    cudaFuncSetAttribute(mma_gemm<2>, cudaFuncAttributeMaxDynamicSharedMemorySize, GSMEM);
    cudaFuncSetAttribute(mma_gemm<3>, cudaFuncAttributeMaxDynamicSharedMemorySize, GSMEM);

    ln_kernel<<<SQ, 256>>>(x, ln1_w, ln1_b, hn, nullptr);
    mma_gemm<0><<<dim3(H3/BN, SQ/BM), 256, GSMEM>>>(hn, in_proj_w, in_proj_b, nullptr, qkv, SQ, H3, HID);
    flash_kernel<<<dim3(SQ/FBM, NH), 256>>>(qkv, attn);
    mma_gemm<1><<<dim3(HID/BN, SQ/BM), 256, GSMEM>>>(attn, out_proj_w, out_proj_b, x, x1, SQ, HID, HID);
    ln_kernel<<<SQ, 256>>>(x1, ln2_w, ln2_b, hn2, hn2f);
    router_kernel<<<SQ, 256>>>(hn2f, router_w);
    build_lists_kernel<<<NE, 256>>>();
    mma_gemm<2><<<dim3(FF/BN, SQ/BM, NE), 256, GSMEM>>>(hn2, w1, nullptr, nullptr, nullptr, SQ, FF, HID);
    mma_gemm<3><<<dim3(HID/BN, SQ/BM, NE), 256, GSMEM>>>(nullptr, w2, nullptr, nullptr, nullptr, SQ, HID, FF);
    final_kernel<<<(SQ*HID)/256, 256>>>(out);
}

// round 10
// speedup vs baseline: 1.7894x; 1.5423x over previous
#include <cuda_runtime.h>
#include <cuda_fp16.h>
#include <math.h>
#include <stdint.h>

#define SQ   2048
#define HID  1024
#define NH   16
#define HD   64
#define H3   3072
#define NE   8
#define TK   2
#define FF   2048

// ---------------- scratch ----------------
__device__ __half g_hn  [SQ*HID];
__device__ __half g_qkv [SQ*H3];
__device__ __half g_attn[SQ*HID];
__device__ float  g_x1  [SQ*HID];
__device__ __half g_hn2 [SQ*HID];
__device__ float  g_hn2f[SQ*HID];
__device__ int    g_topi[SQ*TK];
__device__ float  g_topw[SQ*TK];
__device__ int    g_tok [NE*SQ];
__device__ float  g_gate[NE*SQ];
__device__ int    g_slot[NE*SQ];
__device__ int    g_cnt [NE];
__device__ __half g_h1  [(size_t)NE*SQ*FF];
__device__ float  g_y2  [SQ*TK*HID];
// half weights (converted per launch)
__device__ __half g_wqkv[H3*HID];
__device__ __half g_wout[HID*HID];
__device__ __half g_w1h [(size_t)NE*HID*FF];
__device__ __half g_w2h [(size_t)NE*FF*HID];

// ---------------- helpers ----------------
__device__ __forceinline__ void mmah(float* c, uint32_t a0, uint32_t a1, uint32_t a2,
                                     uint32_t a3, uint32_t b0, uint32_t b1) {
    asm volatile("mma.sync.aligned.m16n8k16.row.col.f32.f16.f16.f32 "
        "{%0,%1,%2,%3},{%4,%5,%6,%7},{%8,%9},{%0,%1,%2,%3};\n"
        : "+f"(c[0]), "+f"(c[1]), "+f"(c[2]), "+f"(c[3])
        : "r"(a0), "r"(a1), "r"(a2), "r"(a3), "r"(b0), "r"(b1));
}
__device__ __forceinline__ uint32_t f2h2(float a, float b) {
    __half2 h = __floats2half2_rn(a, b); return *(uint32_t*)&h;
}
__device__ __forceinline__ uint32_t ldh2(const __half* p) {
    return *(const uint32_t*)p;
}
__device__ __forceinline__ uint32_t pk2(__half a, __half b) {
    __half2 h = __halves2half2(a, b); return *(uint32_t*)&h;
}
__device__ __forceinline__ uint32_t sptr(const void* p) {
    return (uint32_t)__cvta_generic_to_shared(p);
}
__device__ __forceinline__ void cp16(uint32_t s, const void* g, bool v) {
    int sz = v ? 16 : 0;
    asm volatile("cp.async.cg.shared.global [%0], [%1], 16, %2;\n"
                 :: "r"(s), "l"(g), "r"(sz));
}
#define CP_COMMIT() asm volatile("cp.async.commit_group;\n")
#define CP_WAIT1()  asm volatile("cp.async.wait_group 1;\n")

__device__ __forceinline__ float gelu_exact(float x) {
    return 0.5f * x * (1.0f + erff(x * 0.70710678118654752f));
}

// ---------------- weight convert: f32 -> f16 ----------------
__global__ void cvt_kernel(const float* __restrict__ s, __half* __restrict__ d, int n) {
    int i = (blockIdx.x * 256 + threadIdx.x) * 4;
    if (i < n) {
        float4 v = *(const float4*)(s + i);
        *(__half2*)(d + i)     = __floats2half2_rn(v.x, v.y);
        *(__half2*)(d + i + 2) = __floats2half2_rn(v.z, v.w);
    }
}

// ---------------- layernorm: half output + optional f32 copy ----------------
__global__ void ln_kernel(const float* __restrict__ x, const float* __restrict__ w,
                          const float* __restrict__ b, __half* __restrict__ out,
                          float* __restrict__ out_full) {
    int t = blockIdx.x, tid = threadIdx.x;
    float4 v = ((const float4*)(x + (size_t)t*HID))[tid];
    __shared__ float red[256];
    red[tid] = v.x+v.y+v.z+v.w; __syncthreads();
    for (int o = 128; o > 0; o >>= 1) { if (tid < o) red[tid] += red[tid+o]; __syncthreads(); }
    float mu = red[0] * (1.0f/HID); __syncthreads();
    float dx=v.x-mu, dy=v.y-mu, dz=v.z-mu, dw=v.w-mu;
    red[tid] = dx*dx+dy*dy+dz*dz+dw*dw; __syncthreads();
    for (int o = 128; o > 0; o >>= 1) { if (tid < o) red[tid] += red[tid+o]; __syncthreads(); }
    float rstd = rsqrtf(red[0] * (1.0f/HID) + 1e-5f);
    float4 wv = ((const float4*)w)[tid];
    float4 bv = ((const float4*)b)[tid];
    float fx = dx*rstd*wv.x + bv.x, fy = dy*rstd*wv.y + bv.y;
    float fz = dz*rstd*wv.z + bv.z, fw = dw*rstd*wv.w + bv.w;
    if (out_full) {
        float4 f4; f4.x=fx; f4.y=fy; f4.z=fz; f4.w=fw;
        ((float4*)(out_full + (size_t)t*HID))[tid] = f4;
    }
    __half2* oh = (__half2*)(out + (size_t)t*HID);
    oh[tid*2]   = __floats2half2_rn(fx, fy);
    oh[tid*2+1] = __floats2half2_rn(fz, fw);
}

// ===== fp16 m16n8k16 GEMM: 128x128 block, 64x32 warp tile, 3-stage, BK=32 =====
// MODE 0: QKV (NT,+bias, half out)  MODE 1: OUT (NT,+bias+res, f32 out)
// MODE 2: MOE1 (NN, gather, gelu -> half)  MODE 3: MOE2 (NN, gate*scatter -> f32)
#define BM 128
#define BN 128
#define BKh 32
#define NSTG 3
#define ASTRH 40      // A/NT-B row stride in halves (20 h2; 20 mod 32 pattern conflict-free)
#define BSTRNN 136    // NN B row stride in halves
#define STG_H 10240   // halves per stage (A 5120 + B 5120)
#define GSMEM (NSTG*STG_H*2)

template<int MODE>
__global__ void __launch_bounds__(256,2) mma_gemm(
        const __half* __restrict__ A, const __half* __restrict__ Bm,
        const float* __restrict__ bias, const float* __restrict__ res,
        void* __restrict__ Cv, int M, int N, int Kd) {
    extern __shared__ __half sm[];
    int tid = threadIdx.x, wid = tid>>5, lid = tid&31;
    int g = lid>>2, tg = lid&3;
    int wm = (wid>>2)*64, wn = (wid&3)*32;
    int n0 = blockIdx.x*BN, m0 = blockIdx.y*BM;

    int e = 0, cnt = M;
    if (MODE >= 2) { e = blockIdx.z; cnt = g_cnt[e]; if (m0 >= cnt) return; }

    // A: 128 rows x 32 halves; 2 threads/row, 32B each (2 cp16)
    int arow = tid>>1;
    int ka   = (tid&1)*16;   // halves
    const __half* Aptr = A;
    bool av = true;
    if (MODE <= 1) {
        Aptr = A + (size_t)(m0+arow)*Kd;
    } else if (MODE == 2) {
        int t = (m0+arow < cnt) ? g_tok[e*SQ + m0 + arow] : -1;
        av = (t >= 0);
        Aptr = A + (size_t)(av ? t : 0)*Kd;
    } else {
        int rr = m0 + arow; if (rr > SQ-1) rr = SQ-1;
        Aptr = g_h1 + (size_t)(e*SQ + rr)*Kd;
    }
    const __half* Bbase = Bm;
    if (MODE >= 2) Bbase += (size_t)e * Kd * N;

    // B NN: 32 k-rows x 128 halves; 8 threads/row, 32B each
    int bkr = tid>>3, bnc = (tid&7)*16;

    auto issue = [&](int kt, int s) {
        __half* As = sm + s*STG_H;
        __half* Bs = As + 5120;
        uint32_t da = sptr(&As[arow*ASTRH + ka]);
        const __half* ga = Aptr + kt*BKh + ka;
        cp16(da,      ga,     av);
        cp16(da + 16, ga + 8, av);
        if (MODE <= 1) {
            uint32_t db = sptr(&Bs[arow*ASTRH + ka]);
            const __half* gb = Bbase + (size_t)(n0+arow)*Kd + kt*BKh + ka;
            cp16(db,      gb,     true);
            cp16(db + 16, gb + 8, true);
        } else {
            uint32_t db = sptr(&Bs[bkr*BSTRNN + bnc]);
            const __half* gb = Bbase + (size_t)(kt*BKh+bkr)*N + n0 + bnc;
            cp16(db,      gb,     true);
            cp16(db + 16, gb + 8, true);
        }
        CP_COMMIT();
    };

    float acc[4][4][4] = {};
    int KT = Kd / BKh;
    issue(0, 0);
    issue(1, 1);
    int slot = 0;
    for (int kt = 0; kt < KT; kt++) {
        CP_WAIT1();
        __syncthreads();
        {
            int nk = kt + 2;
            if (nk < KT) { int ns = slot + 2; if (ns >= NSTG) ns -= NSTG; issue(nk, ns); }
            else CP_COMMIT();
        }
        const __half* as = sm + slot*STG_H;
        const __half* bs = as + 5120;
#pragma unroll
        for (int ks = 0; ks < 2; ks++) {
            int k0 = ks*16;   // halves
            uint32_t af[4][4], bf[4][2];
#pragma unroll
            for (int mi = 0; mi < 4; mi++) {
                int rb = wm + mi*16;
                af[mi][0] = ldh2(&as[(rb+g  )*ASTRH + k0 + 2*tg]);
                af[mi][1] = ldh2(&as[(rb+g+8)*ASTRH + k0 + 2*tg]);
                af[mi][2] = ldh2(&as[(rb+g  )*ASTRH + k0 + 2*tg + 8]);
                af[mi][3] = ldh2(&as[(rb+g+8)*ASTRH + k0 + 2*tg + 8]);
            }
#pragma unroll
            for (int ni = 0; ni < 4; ni++) {
                int nc = wn + ni*8 + g;
                if (MODE <= 1) {
                    bf[ni][0] = ldh2(&bs[nc*ASTRH + k0 + 2*tg]);
                    bf[ni][1] = ldh2(&bs[nc*ASTRH + k0 + 2*tg + 8]);
                } else {
                    bf[ni][0] = pk2(bs[(k0+2*tg  )*BSTRNN + nc], bs[(k0+2*tg+1)*BSTRNN + nc]);
                    bf[ni][1] = pk2(bs[(k0+2*tg+8)*BSTRNN + nc], bs[(k0+2*tg+9)*BSTRNN + nc]);
                }
            }
#pragma unroll
            for (int mi = 0; mi < 4; mi++)
#pragma unroll
                for (int ni = 0; ni < 4; ni++)
                    mmah(acc[mi][ni], af[mi][0], af[mi][1], af[mi][2], af[mi][3],
                         bf[ni][0], bf[ni][1]);
        }
        if (++slot == NSTG) slot = 0;
    }

    // ---- epilogue ----
#pragma unroll
    for (int mi = 0; mi < 4; mi++) {
        int r1 = m0 + wm + mi*16 + g;
        int r2 = r1 + 8;
#pragma unroll
        for (int ni = 0; ni < 4; ni++) {
            int cc = n0 + wn + ni*8 + 2*tg;
            float* a = acc[mi][ni];
            if (MODE == 0) {
                __half* C = (__half*)Cv;
                float b0 = bias[cc], b1 = bias[cc+1];
                *(__half2*)(C + (size_t)r1*N + cc) = __floats2half2_rn(a[0]+b0, a[1]+b1);
                *(__half2*)(C + (size_t)r2*N + cc) = __floats2half2_rn(a[2]+b0, a[3]+b1);
            } else if (MODE == 1) {
                float* C = (float*)Cv;
                float b0 = bias[cc], b1 = bias[cc+1];
                float v00 = a[0]+b0 + res[(size_t)r1*N + cc];
                float v01 = a[1]+b1 + res[(size_t)r1*N + cc+1];
                float v10 = a[2]+b0 + res[(size_t)r2*N + cc];
                float v11 = a[3]+b1 + res[(size_t)r2*N + cc+1];
                *(float2*)(C + (size_t)r1*N + cc) = make_float2(v00, v01);
                *(float2*)(C + (size_t)r2*N + cc) = make_float2(v10, v11);
            } else if (MODE == 2) {
                if (r1 < cnt)
                    *(__half2*)(&g_h1[(size_t)(e*SQ + r1)*FF + cc]) =
                        __floats2half2_rn(gelu_exact(a[0]), gelu_exact(a[1]));
                if (r2 < cnt)
                    *(__half2*)(&g_h1[(size_t)(e*SQ + r2)*FF + cc]) =
                        __floats2half2_rn(gelu_exact(a[2]), gelu_exact(a[3]));
            } else {
                if (r1 < cnt) {
                    int t = g_tok[e*SQ+r1], sl = g_slot[e*SQ+r1];
                    float gt = g_gate[e*SQ+r1];
                    *(float2*)(&g_y2[((size_t)t*TK+sl)*HID + cc]) =
                        make_float2(gt*a[0], gt*a[1]);
                }
                if (r2 < cnt) {
                    int t = g_tok[e*SQ+r2], sl = g_slot[e*SQ+r2];
                    float gt = g_gate[e*SQ+r2];
                    *(float2*)(&g_y2[((size_t)t*TK+sl)*HID + cc]) =
                        make_float2(gt*a[2], gt*a[3]);
                }
            }
        }
    }
}

// ================= flash attention (fp16 mma, online softmax) =================
#define FBM 128
#define KVSTR 72   // halves per row (36 h2; 36 mod 32 = 4 -> conflict-free)
__global__ void __launch_bounds__(256) flash_kernel(const __half* __restrict__ qkv,
                                                    __half* __restrict__ attn) {
    int h = blockIdx.y;
    int q0 = blockIdx.x * FBM;
    int tid = threadIdx.x, wid = tid>>5, lid = tid&31;
    int wm = wid*16;
    int g = lid>>2, tg = lid&3;
    __shared__ __half Kv[64*KVSTR];
    __shared__ __half Vs[64*KVSTR];

    // Q fragments: 16 rows x 64 d as 4 k-chunks of m16n8k16 A-frags, scaled by 1/8
    uint32_t qf[4][4];
    {
        const __half* Q = qkv + (size_t)(q0+wm)*H3 + h*HD;
        __half2 sc = __float2half2_rn(0.125f);
#pragma unroll
        for (int kc = 0; kc < 4; kc++) {
            int c = kc*16 + 2*tg;
            __half2 h0 = *(const __half2*)&Q[(size_t)g*H3     + c];
            __half2 h1 = *(const __half2*)&Q[(size_t)(g+8)*H3 + c];
            __half2 h2 = *(const __half2*)&Q[(size_t)g*H3     + c + 8];
            __half2 h3 = *(const __half2*)&Q[(size_t)(g+8)*H3 + c + 8];
            h0 = __hmul2(h0, sc); h1 = __hmul2(h1, sc);
            h2 = __hmul2(h2, sc); h3 = __hmul2(h3, sc);
            qf[kc][0] = *(uint32_t*)&h0; qf[kc][1] = *(uint32_t*)&h1;
            qf[kc][2] = *(uint32_t*)&h2; qf[kc][3] = *(uint32_t*)&h3;
        }
    }

    float Oc[8][4] = {};
    float m1 = -1e30f, m2 = -1e30f, l1 = 0.f, l2 = 0.f;
    int r1 = q0 + wm + g, r2 = r1 + 8;

    for (int j0 = 0; j0 < q0 + FBM; j0 += 64) {
        __syncthreads();
        {
            int r = tid & 63;
            int cb = (tid >> 6) * 16;   // halves
            const __half* K = qkv + (size_t)(j0+r)*H3 + HID   + h*HD;
            const __half* V = qkv + (size_t)(j0+r)*H3 + 2*HID + h*HD;
            *(uint4*)(&Kv[r*KVSTR + cb])     = *(const uint4*)(K + cb);
            *(uint4*)(&Kv[r*KVSTR + cb + 8]) = *(const uint4*)(K + cb + 8);
            *(uint4*)(&Vs[r*KVSTR + cb])     = *(const uint4*)(V + cb);
            *(uint4*)(&Vs[r*KVSTR + cb + 8]) = *(const uint4*)(V + cb + 8);
        }
        __syncthreads();

        // S = Q K^T  (8 n-tiles x 4 k-chunks)
        float Sc[8][4];
#pragma unroll
        for (int j = 0; j < 8; j++) {
            Sc[j][0] = Sc[j][1] = Sc[j][2] = Sc[j][3] = 0.f;
#pragma unroll
            for (int kc = 0; kc < 4; kc++) {
                uint32_t b0 = ldh2(&Kv[(j*8+g)*KVSTR + kc*16 + 2*tg]);
                uint32_t b1 = ldh2(&Kv[(j*8+g)*KVSTR + kc*16 + 2*tg + 8]);
                mmah(Sc[j], qf[kc][0], qf[kc][1], qf[kc][2], qf[kc][3], b0, b1);
            }
        }
        if (j0 + 63 > q0 + wm) {
#pragma unroll
            for (int j = 0; j < 8; j++) {
                int cb = j0 + j*8 + 2*tg;
                if (cb   > r1) Sc[j][0] = -1e30f;
                if (cb+1 > r1) Sc[j][1] = -1e30f;
                if (cb   > r2) Sc[j][2] = -1e30f;
                if (cb+1 > r2) Sc[j][3] = -1e30f;
            }
        }
        float mx1 = -1e30f, mx2 = -1e30f;
#pragma unroll
        for (int j = 0; j < 8; j++) {
            mx1 = fmaxf(mx1, fmaxf(Sc[j][0], Sc[j][1]));
            mx2 = fmaxf(mx2, fmaxf(Sc[j][2], Sc[j][3]));
        }
        mx1 = fmaxf(mx1, __shfl_xor_sync(0xffffffffu, mx1, 1));
        mx1 = fmaxf(mx1, __shfl_xor_sync(0xffffffffu, mx1, 2));
        mx2 = fmaxf(mx2, __shfl_xor_sync(0xffffffffu, mx2, 1));
        mx2 = fmaxf(mx2, __shfl_xor_sync(0xffffffffu, mx2, 2));
        float nm1 = fmaxf(m1, mx1), nm2 = fmaxf(m2, mx2);
        float al1 = __expf(m1 - nm1), al2 = __expf(m2 - nm2);
        float s1 = 0.f, s2 = 0.f;
#pragma unroll
        for (int j = 0; j < 8; j++) {
            Sc[j][0] = __expf(Sc[j][0] - nm1);
            Sc[j][1] = __expf(Sc[j][1] - nm1);
            Sc[j][2] = __expf(Sc[j][2] - nm2);
            Sc[j][3] = __expf(Sc[j][3] - nm2);
            s1 += Sc[j][0] + Sc[j][1];
            s2 += Sc[j][2] + Sc[j][3];
        }
        s1 += __shfl_xor_sync(0xffffffffu, s1, 1);
        s1 += __shfl_xor_sync(0xffffffffu, s1, 2);
        s2 += __shfl_xor_sync(0xffffffffu, s2, 1);
        s2 += __shfl_xor_sync(0xffffffffu, s2, 2);
        l1 = l1*al1 + s1; l2 = l2*al2 + s2;
        m1 = nm1; m2 = nm2;
#pragma unroll
        for (int jd = 0; jd < 8; jd++) {
            Oc[jd][0] *= al1; Oc[jd][1] *= al1;
            Oc[jd][2] *= al2; Oc[jd][3] *= al2;
        }
        // O += P V : A-frags come straight from this lane's Sc (layout match)
#pragma unroll
        for (int kc = 0; kc < 4; kc++) {
            uint32_t a0 = f2h2(Sc[2*kc  ][0], Sc[2*kc  ][1]);
            uint32_t a1 = f2h2(Sc[2*kc  ][2], Sc[2*kc  ][3]);
            uint32_t a2 = f2h2(Sc[2*kc+1][0], Sc[2*kc+1][1]);
            uint32_t a3 = f2h2(Sc[2*kc+1][2], Sc[2*kc+1][3]);
#pragma unroll
            for (int jd = 0; jd < 8; jd++) {
                int dc = jd*8 + g;
                uint32_t b0 = pk2(Vs[(kc*16+2*tg  )*KVSTR + dc], Vs[(kc*16+2*tg+1)*KVSTR + dc]);
                uint32_t b1 = pk2(Vs[(kc*16+2*tg+8)*KVSTR + dc], Vs[(kc*16+2*tg+9)*KVSTR + dc]);
                mmah(Oc[jd], a0, a1, a2, a3, b0, b1);
            }
        }
    }

    float inv1 = 1.f / l1, inv2 = 1.f / l2;
#pragma unroll
    for (int jd = 0; jd < 8; jd++) {
        int c = h*HD + jd*8 + 2*tg;
        *(__half2*)(attn + (size_t)r1*HID + c) =
            __floats2half2_rn(Oc[jd][0]*inv1, Oc[jd][1]*inv1);
        *(__half2*)(attn + (size_t)r2*HID + c) =
            __floats2half2_rn(Oc[jd][2]*inv2, Oc[jd][3]*inv2);
    }
}

// ---------------- router (full-precision hn2) ----------------
__global__ void router_kernel(const float* __restrict__ hn2, const float* __restrict__ rw) {
    int t = blockIdx.x, tid = threadIdx.x;
    __shared__ float part[NE][256];
    float loc[NE] = {};
    for (int hh = tid; hh < HID; hh += 256) {
        float xv = hn2[(size_t)t*HID + hh];
#pragma unroll
        for (int e = 0; e < NE; e++) loc[e] += xv * rw[e*HID + hh];
    }
#pragma unroll
    for (int e = 0; e < NE; e++) part[e][tid] = loc[e];
    __syncthreads();
    for (int o = 128; o > 0; o >>= 1) {
        if (tid < o)
#pragma unroll
            for (int e = 0; e < NE; e++) part[e][tid] += part[e][tid+o];
        __syncthreads();
    }
    if (tid == 0) {
        float lg[NE], mx = -1e30f;
#pragma unroll
        for (int e = 0; e < NE; e++) { lg[e] = part[e][0]; mx = fmaxf(mx, lg[e]); }
        float s = 0.f;
#pragma unroll
        for (int e = 0; e < NE; e++) { lg[e] = expf(lg[e]-mx); s += lg[e]; }
        float inv = 1.0f/s;
#pragma unroll
        for (int e = 0; e < NE; e++) lg[e] *= inv;
        int i0 = 0; float v0 = lg[0];
#pragma unroll
        for (int e = 1; e < NE; e++) if (lg[e] > v0) { v0 = lg[e]; i0 = e; }
        int i1 = -1; float v1 = -1e30f;
#pragma unroll
        for (int e = 0; e < NE; e++) if (e != i0 && lg[e] > v1) { v1 = lg[e]; i1 = e; }
        g_topi[t*TK+0] = i0; g_topw[t*TK+0] = v0;
        g_topi[t*TK+1] = i1; g_topw[t*TK+1] = v1;
    }
}

// ---------------- deterministic expert lists ----------------
__global__ void build_lists_kernel() {
    int e = blockIdx.x, tid = threadIdx.x;
    const int CH = SQ / 256;
    int ids[CH], slots[CH]; float gs[CH];
    int loc = 0;
    for (int c = 0; c < CH; c++) {
        int t = tid*CH + c;
        if (g_topi[t*TK+0] == e)      { ids[loc]=t; slots[loc]=0; gs[loc]=g_topw[t*TK+0]; loc++; }
        else if (g_topi[t*TK+1] == e) { ids[loc]=t; slots[loc]=1; gs[loc]=g_topw[t*TK+1]; loc++; }
    }
    __shared__ int sc[256];
    sc[tid] = loc; __syncthreads();
    for (int o = 1; o < 256; o <<= 1) {
        int v = (tid >= o) ? sc[tid-o] : 0;
        __syncthreads();
        sc[tid] += v;
        __syncthreads();
    }
    int off = sc[tid] - loc;
    for (int c = 0; c < loc; c++) {
        g_tok [e*SQ + off + c] = ids[c];
        g_slot[e*SQ + off + c] = slots[c];
        g_gate[e*SQ + off + c] = gs[c];
    }
    if (tid == 255) g_cnt[e] = sc[255];
}

// ---------------- out = x1 + y2[:,0] + y2[:,1] ----------------
__global__ void final_kernel(float* __restrict__ out) {
    int idx = blockIdx.x * 256 + threadIdx.x;
    int t = idx / HID, hh = idx % HID;
    out[idx] = g_x1[idx] + g_y2[((size_t)t*TK)*HID + hh] + g_y2[((size_t)t*TK + 1)*HID + hh];
}

// ---------------- launch ----------------
extern "C" void kernel_launch(void* const* d_in, const int* in_sizes, int n_in,
                              void* d_out, int out_size) {
    (void)in_sizes; (void)n_in; (void)out_size;
    const float* x          = (const float*)d_in[0];
    const float* ln1_w      = (const float*)d_in[1];
    const float* ln1_b      = (const float*)d_in[2];
    const float* in_proj_w  = (const float*)d_in[3];
    const float* in_proj_b  = (const float*)d_in[4];
    const float* out_proj_w = (const float*)d_in[5];
    const float* out_proj_b = (const float*)d_in[6];
    const float* ln2_w      = (const float*)d_in[7];
    const float* ln2_b      = (const float*)d_in[8];
    const float* router_w   = (const float*)d_in[9];
    const float* w1         = (const float*)d_in[10];
    const float* w2         = (const float*)d_in[11];
    float* out = (float*)d_out;

    __half *hn, *qkv, *attn, *hn2, *wqkv, *wout, *w1h, *w2h;
    float *x1, *hn2f;
    cudaGetSymbolAddress((void**)&hn,   g_hn);
    cudaGetSymbolAddress((void**)&qkv,  g_qkv);
    cudaGetSymbolAddress((void**)&attn, g_attn);
    cudaGetSymbolAddress((void**)&x1,   g_x1);
    cudaGetSymbolAddress((void**)&hn2,  g_hn2);
    cudaGetSymbolAddress((void**)&hn2f, g_hn2f);
    cudaGetSymbolAddress((void**)&wqkv, g_wqkv);
    cudaGetSymbolAddress((void**)&wout, g_wout);
    cudaGetSymbolAddress((void**)&w1h,  g_w1h);
    cudaGetSymbolAddress((void**)&w2h,  g_w2h);

    cudaFuncSetAttribute(mma_gemm<0>, cudaFuncAttributeMaxDynamicSharedMemorySize, GSMEM);
    cudaFuncSetAttribute(mma_gemm<1>, cudaFuncAttributeMaxDynamicSharedMemorySize, GSMEM);
    cudaFuncSetAttribute(mma_gemm<2>, cudaFuncAttributeMaxDynamicSharedMemorySize, GSMEM);
    cudaFuncSetAttribute(mma_gemm<3>, cudaFuncAttributeMaxDynamicSharedMemorySize, GSMEM);

    // weight conversion (deterministic, every launch)
    cvt_kernel<<<(H3*HID/4+255)/256, 256>>>(in_proj_w, wqkv, H3*HID);
    cvt_kernel<<<(HID*HID/4+255)/256, 256>>>(out_proj_w, wout, HID*HID);
    cvt_kernel<<<(NE*HID*FF/4+255)/256, 256>>>(w1, w1h, NE*HID*FF);
    cvt_kernel<<<(NE*FF*HID/4+255)/256, 256>>>(w2, w2h, NE*FF*HID);

    ln_kernel<<<SQ, 256>>>(x, ln1_w, ln1_b, hn, nullptr);
    mma_gemm<0><<<dim3(H3/BN, SQ/BM), 256, GSMEM>>>(hn, wqkv, in_proj_b, nullptr, qkv, SQ, H3, HID);
    flash_kernel<<<dim3(SQ/FBM, NH), 256>>>(qkv, attn);
    mma_gemm<1><<<dim3(HID/BN, SQ/BM), 256, GSMEM>>>(attn, wout, out_proj_b, x, x1, SQ, HID, HID);
    ln_kernel<<<SQ, 256>>>(x1, ln2_w, ln2_b, hn2, hn2f);
    router_kernel<<<SQ, 256>>>(hn2f, router_w);
    build_lists_kernel<<<NE, 256>>>();
    mma_gemm<2><<<dim3(FF/BN, SQ/BM, NE), 256, GSMEM>>>(hn2, w1h, nullptr, nullptr, nullptr, SQ, FF, HID);
    mma_gemm<3><<<dim3(HID/BN, SQ/BM, NE), 256, GSMEM>>>(nullptr, w2h, nullptr, nullptr, nullptr, SQ, HID, FF);
    final_kernel<<<(SQ*HID)/256, 256>>>(out);
}

// round 11
// speedup vs baseline: 2.0911x; 1.1686x over previous
#include <cuda_runtime.h>
#include <cuda_fp16.h>
#include <math.h>
#include <stdint.h>

#define SQ   2048
#define HID  1024
#define NH   16
#define HD   64
#define H3   3072
#define NE   8
#define TK   2
#define FF   2048

// ---------------- scratch ----------------
__device__ __half g_hn  [SQ*HID];
__device__ __half g_qkv [SQ*H3];
__device__ __half g_attn[SQ*HID];
__device__ float  g_x1  [SQ*HID];
__device__ __half g_hn2 [SQ*HID];
__device__ float  g_hn2f[SQ*HID];
__device__ int    g_topi[SQ*TK];
__device__ float  g_topw[SQ*TK];
__device__ int    g_tok [NE*SQ];
__device__ float  g_gate[NE*SQ];
__device__ int    g_slot[NE*SQ];
__device__ int    g_cnt [NE];
__device__ __half g_h1  [(size_t)NE*SQ*FF];
__device__ float  g_y2  [SQ*TK*HID];
__device__ __half g_wqkv[H3*HID];
__device__ __half g_wout[HID*HID];
__device__ __half g_w1h [(size_t)NE*HID*FF];
__device__ __half g_w2h [(size_t)NE*FF*HID];

// ---------------- helpers ----------------
__device__ __forceinline__ void mmah(float* c, uint32_t a0, uint32_t a1, uint32_t a2,
                                     uint32_t a3, uint32_t b0, uint32_t b1) {
    asm volatile("mma.sync.aligned.m16n8k16.row.col.f32.f16.f16.f32 "
        "{%0,%1,%2,%3},{%4,%5,%6,%7},{%8,%9},{%0,%1,%2,%3};\n"
        : "+f"(c[0]), "+f"(c[1]), "+f"(c[2]), "+f"(c[3])
        : "r"(a0), "r"(a1), "r"(a2), "r"(a3), "r"(b0), "r"(b1));
}
__device__ __forceinline__ void ldsm4(uint32_t& r0, uint32_t& r1, uint32_t& r2,
                                      uint32_t& r3, uint32_t addr) {
    asm volatile("ldmatrix.sync.aligned.m8n8.x4.shared.b16 {%0,%1,%2,%3}, [%4];"
        : "=r"(r0), "=r"(r1), "=r"(r2), "=r"(r3) : "r"(addr));
}
__device__ __forceinline__ void ldsm4t(uint32_t& r0, uint32_t& r1, uint32_t& r2,
                                       uint32_t& r3, uint32_t addr) {
    asm volatile("ldmatrix.sync.aligned.m8n8.x4.trans.shared.b16 {%0,%1,%2,%3}, [%4];"
        : "=r"(r0), "=r"(r1), "=r"(r2), "=r"(r3) : "r"(addr));
}
__device__ __forceinline__ uint32_t f2h2(float a, float b) {
    __half2 h = __floats2half2_rn(a, b); return *(uint32_t*)&h;
}
__device__ __forceinline__ uint32_t sptr(const void* p) {
    return (uint32_t)__cvta_generic_to_shared(p);
}
__device__ __forceinline__ void cp16(uint32_t s, const void* g, bool v) {
    int sz = v ? 16 : 0;
    asm volatile("cp.async.cg.shared.global [%0], [%1], 16, %2;\n"
                 :: "r"(s), "l"(g), "r"(sz));
}
#define CP_COMMIT() asm volatile("cp.async.commit_group;\n")
#define CP_WAIT1()  asm volatile("cp.async.wait_group 1;\n")

__device__ __forceinline__ float gelu_exact(float x) {
    return 0.5f * x * (1.0f + erff(x * 0.70710678118654752f));
}

// ---------------- weight convert: f32 -> f16, 8 elems/thread ----------------
__global__ void cvt_kernel(const float* __restrict__ s, __half* __restrict__ d, int n) {
    int i = (blockIdx.x * 256 + threadIdx.x) * 8;
    if (i < n) {
        float4 v0 = *(const float4*)(s + i);
        float4 v1 = *(const float4*)(s + i + 4);
        __half2 h0 = __floats2half2_rn(v0.x, v0.y);
        __half2 h1 = __floats2half2_rn(v0.z, v0.w);
        __half2 h2 = __floats2half2_rn(v1.x, v1.y);
        __half2 h3 = __floats2half2_rn(v1.z, v1.w);
        uint4 o;
        o.x = *(uint32_t*)&h0; o.y = *(uint32_t*)&h1;
        o.z = *(uint32_t*)&h2; o.w = *(uint32_t*)&h3;
        *(uint4*)(d + i) = o;
    }
}

// ---------------- layernorm: half output + optional f32 copy ----------------
__global__ void ln_kernel(const float* __restrict__ x, const float* __restrict__ w,
                          const float* __restrict__ b, __half* __restrict__ out,
                          float* __restrict__ out_full) {
    int t = blockIdx.x, tid = threadIdx.x;
    float4 v = ((const float4*)(x + (size_t)t*HID))[tid];
    __shared__ float red[256];
    red[tid] = v.x+v.y+v.z+v.w; __syncthreads();
    for (int o = 128; o > 0; o >>= 1) { if (tid < o) red[tid] += red[tid+o]; __syncthreads(); }
    float mu = red[0] * (1.0f/HID); __syncthreads();
    float dx=v.x-mu, dy=v.y-mu, dz=v.z-mu, dw=v.w-mu;
    red[tid] = dx*dx+dy*dy+dz*dz+dw*dw; __syncthreads();
    for (int o = 128; o > 0; o >>= 1) { if (tid < o) red[tid] += red[tid+o]; __syncthreads(); }
    float rstd = rsqrtf(red[0] * (1.0f/HID) + 1e-5f);
    float4 wv = ((const float4*)w)[tid];
    float4 bv = ((const float4*)b)[tid];
    float fx = dx*rstd*wv.x + bv.x, fy = dy*rstd*wv.y + bv.y;
    float fz = dz*rstd*wv.z + bv.z, fw = dw*rstd*wv.w + bv.w;
    if (out_full) {
        float4 f4; f4.x=fx; f4.y=fy; f4.z=fz; f4.w=fw;
        ((float4*)(out_full + (size_t)t*HID))[tid] = f4;
    }
    __half2* oh = (__half2*)(out + (size_t)t*HID);
    oh[tid*2]   = __floats2half2_rn(fx, fy);
    oh[tid*2+1] = __floats2half2_rn(fz, fw);
}

// ===== fp16 m16n8k16 GEMM with ldmatrix: 128x128 block, 64x32 warp tile =====
#define BM 128
#define BN 128
#define BKh 32
#define NSTG 3
#define ASTRH 40      // halves; 80B row stride (banks: +20 words, conflict-free)
#define BSTRNN 136    // halves; 272B row stride (banks: +4 words, conflict-free)
#define STG_H 10240
#define GSMEM (NSTG*STG_H*2)

template<int MODE>
__global__ void __launch_bounds__(256,2) mma_gemm(
        const __half* __restrict__ A, const __half* __restrict__ Bm,
        const float* __restrict__ bias, const float* __restrict__ res,
        void* __restrict__ Cv, int M, int N, int Kd) {
    extern __shared__ __half sm[];
    int tid = threadIdx.x, wid = tid>>5, lid = tid&31;
    int g = lid>>2, tg = lid&3;
    int lrow = lid & 7, grp = lid >> 3;
    int wm = (wid>>2)*64, wn = (wid&3)*32;
    int n0 = blockIdx.x*BN, m0 = blockIdx.y*BM;

    int e = 0, cnt = M;
    if (MODE >= 2) { e = blockIdx.z; cnt = g_cnt[e]; if (m0 >= cnt) return; }

    int arow = tid>>1;
    int ka   = (tid&1)*16;
    const __half* Aptr = A;
    bool av = true;
    if (MODE <= 1) {
        Aptr = A + (size_t)(m0+arow)*Kd;
    } else if (MODE == 2) {
        int t = (m0+arow < cnt) ? g_tok[e*SQ + m0 + arow] : -1;
        av = (t >= 0);
        Aptr = A + (size_t)(av ? t : 0)*Kd;
    } else {
        int rr = m0 + arow; if (rr > SQ-1) rr = SQ-1;
        Aptr = g_h1 + (size_t)(e*SQ + rr)*Kd;
    }
    const __half* Bbase = Bm;
    if (MODE >= 2) Bbase += (size_t)e * Kd * N;

    int bkr = tid>>3, bnc = (tid&7)*16;

    auto issue = [&](int kt, int s) {
        __half* As = sm + s*STG_H;
        __half* Bs = As + 5120;
        uint32_t da = sptr(&As[arow*ASTRH + ka]);
        const __half* ga = Aptr + kt*BKh + ka;
        cp16(da,      ga,     av);
        cp16(da + 16, ga + 8, av);
        if (MODE <= 1) {
            uint32_t db = sptr(&Bs[arow*ASTRH + ka]);
            const __half* gb = Bbase + (size_t)(n0+arow)*Kd + kt*BKh + ka;
            cp16(db,      gb,     true);
            cp16(db + 16, gb + 8, true);
        } else {
            uint32_t db = sptr(&Bs[bkr*BSTRNN + bnc]);
            const __half* gb = Bbase + (size_t)(kt*BKh+bkr)*N + n0 + bnc;
            cp16(db,      gb,     true);
            cp16(db + 16, gb + 8, true);
        }
        CP_COMMIT();
    };

    float acc[4][4][4] = {};
    int KT = Kd / BKh;
    issue(0, 0);
    issue(1, 1);
    int slot = 0;
    for (int kt = 0; kt < KT; kt++) {
        CP_WAIT1();
        __syncthreads();
        {
            int nk = kt + 2;
            if (nk < KT) { int ns = slot + 2; if (ns >= NSTG) ns -= NSTG; issue(nk, ns); }
            else CP_COMMIT();
        }
        const __half* as = sm + slot*STG_H;
        const __half* bs = as + 5120;
#pragma unroll
        for (int ks = 0; ks < 2; ks++) {
            int k0 = ks*16;
            uint32_t af[4][4], bf[4][2];
#pragma unroll
            for (int mi = 0; mi < 4; mi++) {
                // x4: m0 rows rb+lrow@k0, m1 rows rb+8+lrow@k0, m2 @k0+8, m3 rows+8 @k0+8
                uint32_t ad = sptr(&as[(wm + mi*16 + (grp&1)*8 + lrow)*ASTRH + k0 + (grp>>1)*8]);
                ldsm4(af[mi][0], af[mi][1], af[mi][2], af[mi][3], ad);
            }
#pragma unroll
            for (int np = 0; np < 2; np++) {
                int ni0 = np*2;
                if (MODE <= 1) {
                    // x4: m0=(ni0,k0) m1=(ni0,k0+8) m2=(ni0+1,k0) m3=(ni0+1,k0+8)
                    uint32_t bd = sptr(&bs[(wn + (ni0 + (grp>>1))*8 + lrow)*ASTRH + k0 + (grp&1)*8]);
                    ldsm4(bf[ni0][0], bf[ni0][1], bf[ni0+1][0], bf[ni0+1][1], bd);
                } else {
                    // trans x4: m0=(k0,ni0) m1=(k0+8,ni0) m2=(k0,ni0+1) m3=(k0+8,ni0+1)
                    uint32_t bd = sptr(&bs[(k0 + (grp&1)*8 + lrow)*BSTRNN + wn + (ni0 + (grp>>1))*8]);
                    ldsm4t(bf[ni0][0], bf[ni0][1], bf[ni0+1][0], bf[ni0+1][1], bd);
                }
            }
#pragma unroll
            for (int mi = 0; mi < 4; mi++)
#pragma unroll
                for (int ni = 0; ni < 4; ni++)
                    mmah(acc[mi][ni], af[mi][0], af[mi][1], af[mi][2], af[mi][3],
                         bf[ni][0], bf[ni][1]);
        }
        if (++slot == NSTG) slot = 0;
    }

    // ---- epilogue ----
#pragma unroll
    for (int mi = 0; mi < 4; mi++) {
        int r1 = m0 + wm + mi*16 + g;
        int r2 = r1 + 8;
#pragma unroll
        for (int ni = 0; ni < 4; ni++) {
            int cc = n0 + wn + ni*8 + 2*tg;
            float* a = acc[mi][ni];
            if (MODE == 0) {
                __half* C = (__half*)Cv;
                float b0 = bias[cc], b1 = bias[cc+1];
                *(__half2*)(C + (size_t)r1*N + cc) = __floats2half2_rn(a[0]+b0, a[1]+b1);
                *(__half2*)(C + (size_t)r2*N + cc) = __floats2half2_rn(a[2]+b0, a[3]+b1);
            } else if (MODE == 1) {
                float* C = (float*)Cv;
                float b0 = bias[cc], b1 = bias[cc+1];
                float v00 = a[0]+b0 + res[(size_t)r1*N + cc];
                float v01 = a[1]+b1 + res[(size_t)r1*N + cc+1];
                float v10 = a[2]+b0 + res[(size_t)r2*N + cc];
                float v11 = a[3]+b1 + res[(size_t)r2*N + cc+1];
                *(float2*)(C + (size_t)r1*N + cc) = make_float2(v00, v01);
                *(float2*)(C + (size_t)r2*N + cc) = make_float2(v10, v11);
            } else if (MODE == 2) {
                if (r1 < cnt)
                    *(__half2*)(&g_h1[(size_t)(e*SQ + r1)*FF + cc]) =
                        __floats2half2_rn(gelu_exact(a[0]), gelu_exact(a[1]));
                if (r2 < cnt)
                    *(__half2*)(&g_h1[(size_t)(e*SQ + r2)*FF + cc]) =
                        __floats2half2_rn(gelu_exact(a[2]), gelu_exact(a[3]));
            } else {
                if (r1 < cnt) {
                    int t = g_tok[e*SQ+r1], sl = g_slot[e*SQ+r1];
                    float gt = g_gate[e*SQ+r1];
                    *(float2*)(&g_y2[((size_t)t*TK+sl)*HID + cc]) =
                        make_float2(gt*a[0], gt*a[1]);
                }
                if (r2 < cnt) {
                    int t = g_tok[e*SQ+r2], sl = g_slot[e*SQ+r2];
                    float gt = g_gate[e*SQ+r2];
                    *(float2*)(&g_y2[((size_t)t*TK+sl)*HID + cc]) =
                        make_float2(gt*a[2], gt*a[3]);
                }
            }
        }
    }
}

// ================= flash attention (fp16 mma + ldmatrix) =================
#define FBM 128
#define KVSTR 72   // halves; 144B stride (banks +4 words, conflict-free)
__global__ void __launch_bounds__(256) flash_kernel(const __half* __restrict__ qkv,
                                                    __half* __restrict__ attn) {
    int h = blockIdx.y;
    int q0 = blockIdx.x * FBM;
    int tid = threadIdx.x, wid = tid>>5, lid = tid&31;
    int wm = wid*16;
    int g = lid>>2, tg = lid&3;
    int lrow = lid & 7, grp = lid >> 3;
    __shared__ __half Kv[64*KVSTR];
    __shared__ __half Vs[64*KVSTR];

    uint32_t qf[4][4];
    {
        const __half* Q = qkv + (size_t)(q0+wm)*H3 + h*HD;
        __half2 sc = __float2half2_rn(0.125f);
#pragma unroll
        for (int kc = 0; kc < 4; kc++) {
            int c = kc*16 + 2*tg;
            __half2 h0 = *(const __half2*)&Q[(size_t)g*H3     + c];
            __half2 h1 = *(const __half2*)&Q[(size_t)(g+8)*H3 + c];
            __half2 h2 = *(const __half2*)&Q[(size_t)g*H3     + c + 8];
            __half2 h3 = *(const __half2*)&Q[(size_t)(g+8)*H3 + c + 8];
            h0 = __hmul2(h0, sc); h1 = __hmul2(h1, sc);
            h2 = __hmul2(h2, sc); h3 = __hmul2(h3, sc);
            qf[kc][0] = *(uint32_t*)&h0; qf[kc][1] = *(uint32_t*)&h1;
            qf[kc][2] = *(uint32_t*)&h2; qf[kc][3] = *(uint32_t*)&h3;
        }
    }

    float Oc[8][4] = {};
    float m1 = -1e30f, m2 = -1e30f, l1 = 0.f, l2 = 0.f;
    int r1 = q0 + wm + g, r2 = r1 + 8;

    for (int j0 = 0; j0 < q0 + FBM; j0 += 64) {
        __syncthreads();
        {
            int r = tid & 63;
            int cb = (tid >> 6) * 16;
            const __half* K = qkv + (size_t)(j0+r)*H3 + HID   + h*HD;
            const __half* V = qkv + (size_t)(j0+r)*H3 + 2*HID + h*HD;
            *(uint4*)(&Kv[r*KVSTR + cb])     = *(const uint4*)(K + cb);
            *(uint4*)(&Kv[r*KVSTR + cb + 8]) = *(const uint4*)(K + cb + 8);
            *(uint4*)(&Vs[r*KVSTR + cb])     = *(const uint4*)(V + cb);
            *(uint4*)(&Vs[r*KVSTR + cb + 8]) = *(const uint4*)(V + cb + 8);
        }
        __syncthreads();

        // S = Q K^T
        float Sc[8][4];
#pragma unroll
        for (int j = 0; j < 8; j++) {
            Sc[j][0] = Sc[j][1] = Sc[j][2] = Sc[j][3] = 0.f;
            uint32_t b[8];
            // x4 #1: cols 0..31 -> b0/b1 of kc0, b0/b1 of kc1
            ldsm4(b[0], b[1], b[2], b[3], sptr(&Kv[(j*8+lrow)*KVSTR + grp*8]));
            // x4 #2: cols 32..63 -> kc2, kc3
            ldsm4(b[4], b[5], b[6], b[7], sptr(&Kv[(j*8+lrow)*KVSTR + 32 + grp*8]));
#pragma unroll
            for (int kc = 0; kc < 4; kc++)
                mmah(Sc[j], qf[kc][0], qf[kc][1], qf[kc][2], qf[kc][3],
                     b[kc*2], b[kc*2+1]);
        }
        if (j0 + 63 > q0 + wm) {
#pragma unroll
            for (int j = 0; j < 8; j++) {
                int cb = j0 + j*8 + 2*tg;
                if (cb   > r1) Sc[j][0] = -1e30f;
                if (cb+1 > r1) Sc[j][1] = -1e30f;
                if (cb   > r2) Sc[j][2] = -1e30f;
                if (cb+1 > r2) Sc[j][3] = -1e30f;
            }
        }
        float mx1 = -1e30f, mx2 = -1e30f;
#pragma unroll
        for (int j = 0; j < 8; j++) {
            mx1 = fmaxf(mx1, fmaxf(Sc[j][0], Sc[j][1]));
            mx2 = fmaxf(mx2, fmaxf(Sc[j][2], Sc[j][3]));
        }
        mx1 = fmaxf(mx1, __shfl_xor_sync(0xffffffffu, mx1, 1));
        mx1 = fmaxf(mx1, __shfl_xor_sync(0xffffffffu, mx1, 2));
        mx2 = fmaxf(mx2, __shfl_xor_sync(0xffffffffu, mx2, 1));
        mx2 = fmaxf(mx2, __shfl_xor_sync(0xffffffffu, mx2, 2));
        float nm1 = fmaxf(m1, mx1), nm2 = fmaxf(m2, mx2);
        float al1 = __expf(m1 - nm1), al2 = __expf(m2 - nm2);
        float s1 = 0.f, s2 = 0.f;
#pragma unroll
        for (int j = 0; j < 8; j++) {
            Sc[j][0] = __expf(Sc[j][0] - nm1);
            Sc[j][1] = __expf(Sc[j][1] - nm1);
            Sc[j][2] = __expf(Sc[j][2] - nm2);
            Sc[j][3] = __expf(Sc[j][3] - nm2);
            s1 += Sc[j][0] + Sc[j][1];
            s2 += Sc[j][2] + Sc[j][3];
        }
        s1 += __shfl_xor_sync(0xffffffffu, s1, 1);
        s1 += __shfl_xor_sync(0xffffffffu, s1, 2);
        s2 += __shfl_xor_sync(0xffffffffu, s2, 1);
        s2 += __shfl_xor_sync(0xffffffffu, s2, 2);
        l1 = l1*al1 + s1; l2 = l2*al2 + s2;
        m1 = nm1; m2 = nm2;
#pragma unroll
        for (int jd = 0; jd < 8; jd++) {
            Oc[jd][0] *= al1; Oc[jd][1] *= al1;
            Oc[jd][2] *= al2; Oc[jd][3] *= al2;
        }
        // O += P V  (A from Sc directly; V B-frags via ldmatrix.trans)
#pragma unroll
        for (int kc = 0; kc < 4; kc++) {
            uint32_t a0 = f2h2(Sc[2*kc  ][0], Sc[2*kc  ][1]);
            uint32_t a1 = f2h2(Sc[2*kc  ][2], Sc[2*kc  ][3]);
            uint32_t a2 = f2h2(Sc[2*kc+1][0], Sc[2*kc+1][1]);
            uint32_t a3 = f2h2(Sc[2*kc+1][2], Sc[2*kc+1][3]);
#pragma unroll
            for (int jp = 0; jp < 4; jp++) {
                int jd0 = jp*2;
                uint32_t b0, b1, b2, b3;
                // trans x4: m0=(kv lo,jd0) m1=(kv hi,jd0) m2=(kv lo,jd1) m3=(kv hi,jd1)
                uint32_t vd = sptr(&Vs[(kc*16 + (grp&1)*8 + lrow)*KVSTR + (jd0 + (grp>>1))*8]);
                ldsm4t(b0, b1, b2, b3, vd);
                mmah(Oc[jd0],   a0, a1, a2, a3, b0, b1);
                mmah(Oc[jd0+1], a0, a1, a2, a3, b2, b3);
            }
        }
    }

    float inv1 = 1.f / l1, inv2 = 1.f / l2;
#pragma unroll
    for (int jd = 0; jd < 8; jd++) {
        int c = h*HD + jd*8 + 2*tg;
        *(__half2*)(attn + (size_t)r1*HID + c) =
            __floats2half2_rn(Oc[jd][0]*inv1, Oc[jd][1]*inv1);
        *(__half2*)(attn + (size_t)r2*HID + c) =
            __floats2half2_rn(Oc[jd][2]*inv2, Oc[jd][3]*inv2);
    }
}

// ---------------- router (full-precision hn2) ----------------
__global__ void router_kernel(const float* __restrict__ hn2, const float* __restrict__ rw) {
    int t = blockIdx.x, tid = threadIdx.x;
    __shared__ float part[NE][256];
    float loc[NE] = {};
    for (int hh = tid; hh < HID; hh += 256) {
        float xv = hn2[(size_t)t*HID + hh];
#pragma unroll
        for (int e = 0; e < NE; e++) loc[e] += xv * rw[e*HID + hh];
    }
#pragma unroll
    for (int e = 0; e < NE; e++) part[e][tid] = loc[e];
    __syncthreads();
    for (int o = 128; o > 0; o >>= 1) {
        if (tid < o)
#pragma unroll
            for (int e = 0; e < NE; e++) part[e][tid] += part[e][tid+o];
        __syncthreads();
    }
    if (tid == 0) {
        float lg[NE], mx = -1e30f;
#pragma unroll
        for (int e = 0; e < NE; e++) { lg[e] = part[e][0]; mx = fmaxf(mx, lg[e]); }
        float s = 0.f;
#pragma unroll
        for (int e = 0; e < NE; e++) { lg[e] = expf(lg[e]-mx); s += lg[e]; }
        float inv = 1.0f/s;
#pragma unroll
        for (int e = 0; e < NE; e++) lg[e] *= inv;
        int i0 = 0; float v0 = lg[0];
#pragma unroll
        for (int e = 1; e < NE; e++) if (lg[e] > v0) { v0 = lg[e]; i0 = e; }
        int i1 = -1; float v1 = -1e30f;
#pragma unroll
        for (int e = 0; e < NE; e++) if (e != i0 && lg[e] > v1) { v1 = lg[e]; i1 = e; }
        g_topi[t*TK+0] = i0; g_topw[t*TK+0] = v0;
        g_topi[t*TK+1] = i1; g_topw[t*TK+1] = v1;
    }
}

// ---------------- deterministic expert lists ----------------
__global__ void build_lists_kernel() {
    int e = blockIdx.x, tid = threadIdx.x;
    const int CH = SQ / 256;
    int ids[CH], slots[CH]; float gs[CH];
    int loc = 0;
    for (int c = 0; c < CH; c++) {
        int t = tid*CH + c;
        if (g_topi[t*TK+0] == e)      { ids[loc]=t; slots[loc]=0; gs[loc]=g_topw[t*TK+0]; loc++; }
        else if (g_topi[t*TK+1] == e) { ids[loc]=t; slots[loc]=1; gs[loc]=g_topw[t*TK+1]; loc++; }
    }
    __shared__ int sc[256];
    sc[tid] = loc; __syncthreads();
    for (int o = 1; o < 256; o <<= 1) {
        int v = (tid >= o) ? sc[tid-o] : 0;
        __syncthreads();
        sc[tid] += v;
        __syncthreads();
    }
    int off = sc[tid] - loc;
    for (int c = 0; c < loc; c++) {
        g_tok [e*SQ + off + c] = ids[c];
        g_slot[e*SQ + off + c] = slots[c];
        g_gate[e*SQ + off + c] = gs[c];
    }
    if (tid == 255) g_cnt[e] = sc[255];
}

// ---------------- out = x1 + y2[:,0] + y2[:,1] ----------------
__global__ void final_kernel(float* __restrict__ out) {
    int idx = blockIdx.x * 256 + threadIdx.x;
    int t = idx / HID, hh = idx % HID;
    out[idx] = g_x1[idx] + g_y2[((size_t)t*TK)*HID + hh] + g_y2[((size_t)t*TK + 1)*HID + hh];
}

// ---------------- launch ----------------
extern "C" void kernel_launch(void* const* d_in, const int* in_sizes, int n_in,
                              void* d_out, int out_size) {
    (void)in_sizes; (void)n_in; (void)out_size;
    const float* x          = (const float*)d_in[0];
    const float* ln1_w      = (const float*)d_in[1];
    const float* ln1_b      = (const float*)d_in[2];
    const float* in_proj_w  = (const float*)d_in[3];
    const float* in_proj_b  = (const float*)d_in[4];
    const float* out_proj_w = (const float*)d_in[5];
    const float* out_proj_b = (const float*)d_in[6];
    const float* ln2_w      = (const float*)d_in[7];
    const float* ln2_b      = (const float*)d_in[8];
    const float* router_w   = (const float*)d_in[9];
    const float* w1         = (const float*)d_in[10];
    const float* w2         = (const float*)d_in[11];
    float* out = (float*)d_out;

    __half *hn, *qkv, *attn, *hn2, *wqkv, *wout, *w1h, *w2h;
    float *x1, *hn2f;
    cudaGetSymbolAddress((void**)&hn,   g_hn);
    cudaGetSymbolAddress((void**)&qkv,  g_qkv);
    cudaGetSymbolAddress((void**)&attn, g_attn);
    cudaGetSymbolAddress((void**)&x1,   g_x1);
    cudaGetSymbolAddress((void**)&hn2,  g_hn2);
    cudaGetSymbolAddress((void**)&hn2f, g_hn2f);
    cudaGetSymbolAddress((void**)&wqkv, g_wqkv);
    cudaGetSymbolAddress((void**)&wout, g_wout);
    cudaGetSymbolAddress((void**)&w1h,  g_w1h);
    cudaGetSymbolAddress((void**)&w2h,  g_w2h);

    cudaFuncSetAttribute(mma_gemm<0>, cudaFuncAttributeMaxDynamicSharedMemorySize, GSMEM);
    cudaFuncSetAttribute(mma_gemm<1>, cudaFuncAttributeMaxDynamicSharedMemorySize, GSMEM);
    cudaFuncSetAttribute(mma_gemm<2>, cudaFuncAttributeMaxDynamicSharedMemorySize, GSMEM);
    cudaFuncSetAttribute(mma_gemm<3>, cudaFuncAttributeMaxDynamicSharedMemorySize, GSMEM);

    cvt_kernel<<<(H3*HID/8+255)/256, 256>>>(in_proj_w, wqkv, H3*HID);
    cvt_kernel<<<(HID*HID/8+255)/256, 256>>>(out_proj_w, wout, HID*HID);
    cvt_kernel<<<(NE*HID*FF/8+255)/256, 256>>>(w1, w1h, NE*HID*FF);
    cvt_kernel<<<(NE*FF*HID/8+255)/256, 256>>>(w2, w2h, NE*FF*HID);

    ln_kernel<<<SQ, 256>>>(x, ln1_w, ln1_b, hn, nullptr);
    mma_gemm<0><<<dim3(H3/BN, SQ/BM), 256, GSMEM>>>(hn, wqkv, in_proj_b, nullptr, qkv, SQ, H3, HID);
    flash_kernel<<<dim3(SQ/FBM, NH), 256>>>(qkv, attn);
    mma_gemm<1><<<dim3(HID/BN, SQ/BM), 256, GSMEM>>>(attn, wout, out_proj_b, x, x1, SQ, HID, HID);
    ln_kernel<<<SQ, 256>>>(x1, ln2_w, ln2_b, hn2, hn2f);
    router_kernel<<<SQ, 256>>>(hn2f, router_w);
    build_lists_kernel<<<NE, 256>>>();
    mma_gemm<2><<<dim3(FF/BN, SQ/BM, NE), 256, GSMEM>>>(hn2, w1h, nullptr, nullptr, nullptr, SQ, FF, HID);
    mma_gemm<3><<<dim3(HID/BN, SQ/BM, NE), 256, GSMEM>>>(nullptr, w2h, nullptr, nullptr, nullptr, SQ, HID, FF);
    final_kernel<<<(SQ*HID)/256, 256>>>(out);
}

// round 12
// speedup vs baseline: 2.1353x; 1.0211x over previous
#include <cuda_runtime.h>
#include <cuda_fp16.h>
#include <math.h>
#include <stdint.h>

#define SQ   2048
#define HID  1024
#define NH   16
#define HD   64
#define H3   3072
#define NE   8
#define TK   2
#define FF   2048

// ---------------- scratch ----------------
__device__ __half g_hn  [SQ*HID];
__device__ __half g_qkv [SQ*H3];
__device__ __half g_attn[SQ*HID];
__device__ float  g_x1  [SQ*HID];
__device__ __half g_hn2 [SQ*HID];
__device__ float  g_hn2f[SQ*HID];
__device__ int    g_topi[SQ*TK];
__device__ float  g_topw[SQ*TK];
__device__ int    g_tok [NE*SQ];
__device__ float  g_gate[NE*SQ];
__device__ int    g_slot[NE*SQ];
__device__ int    g_cnt [NE];
__device__ __half g_h1  [(size_t)NE*SQ*FF];
__device__ float  g_y2  [SQ*TK*HID];
__device__ __half g_wqkv[H3*HID];
__device__ __half g_wout[HID*HID];
__device__ __half g_w1h [(size_t)NE*HID*FF];
__device__ __half g_w2h [(size_t)NE*FF*HID];

// ---------------- helpers ----------------
__device__ __forceinline__ void mmah(float* c, uint32_t a0, uint32_t a1, uint32_t a2,
                                     uint32_t a3, uint32_t b0, uint32_t b1) {
    asm volatile("mma.sync.aligned.m16n8k16.row.col.f32.f16.f16.f32 "
        "{%0,%1,%2,%3},{%4,%5,%6,%7},{%8,%9},{%0,%1,%2,%3};\n"
        : "+f"(c[0]), "+f"(c[1]), "+f"(c[2]), "+f"(c[3])
        : "r"(a0), "r"(a1), "r"(a2), "r"(a3), "r"(b0), "r"(b1));
}
__device__ __forceinline__ void ldsm4(uint32_t& r0, uint32_t& r1, uint32_t& r2,
                                      uint32_t& r3, uint32_t addr) {
    asm volatile("ldmatrix.sync.aligned.m8n8.x4.shared.b16 {%0,%1,%2,%3}, [%4];"
        : "=r"(r0), "=r"(r1), "=r"(r2), "=r"(r3) : "r"(addr));
}
__device__ __forceinline__ void ldsm4t(uint32_t& r0, uint32_t& r1, uint32_t& r2,
                                       uint32_t& r3, uint32_t addr) {
    asm volatile("ldmatrix.sync.aligned.m8n8.x4.trans.shared.b16 {%0,%1,%2,%3}, [%4];"
        : "=r"(r0), "=r"(r1), "=r"(r2), "=r"(r3) : "r"(addr));
}
__device__ __forceinline__ uint32_t f2h2(float a, float b) {
    __half2 h = __floats2half2_rn(a, b); return *(uint32_t*)&h;
}
__device__ __forceinline__ uint32_t sptr(const void* p) {
    return (uint32_t)__cvta_generic_to_shared(p);
}
__device__ __forceinline__ void cp16(uint32_t s, const void* g, bool v) {
    int sz = v ? 16 : 0;
    asm volatile("cp.async.cg.shared.global [%0], [%1], 16, %2;\n"
                 :: "r"(s), "l"(g), "r"(sz));
}
#define CP_COMMIT() asm volatile("cp.async.commit_group;\n")
#define CP_WAIT1()  asm volatile("cp.async.wait_group 1;\n")
#define CP_WAIT0()  asm volatile("cp.async.wait_group 0;\n")

__device__ __forceinline__ float gelu_exact(float x) {
    return 0.5f * x * (1.0f + erff(x * 0.70710678118654752f));
}

// ---------------- weight convert ----------------
__global__ void cvt_kernel(const float* __restrict__ s, __half* __restrict__ d, int n) {
    int i = (blockIdx.x * 256 + threadIdx.x) * 8;
    if (i < n) {
        float4 v0 = *(const float4*)(s + i);
        float4 v1 = *(const float4*)(s + i + 4);
        __half2 h0 = __floats2half2_rn(v0.x, v0.y);
        __half2 h1 = __floats2half2_rn(v0.z, v0.w);
        __half2 h2 = __floats2half2_rn(v1.x, v1.y);
        __half2 h3 = __floats2half2_rn(v1.z, v1.w);
        uint4 o;
        o.x = *(uint32_t*)&h0; o.y = *(uint32_t*)&h1;
        o.z = *(uint32_t*)&h2; o.w = *(uint32_t*)&h3;
        *(uint4*)(d + i) = o;
    }
}

// ---------------- layernorm ----------------
__global__ void ln_kernel(const float* __restrict__ x, const float* __restrict__ w,
                          const float* __restrict__ b, __half* __restrict__ out,
                          float* __restrict__ out_full) {
    int t = blockIdx.x, tid = threadIdx.x;
    float4 v = ((const float4*)(x + (size_t)t*HID))[tid];
    __shared__ float red[256];
    red[tid] = v.x+v.y+v.z+v.w; __syncthreads();
    for (int o = 128; o > 0; o >>= 1) { if (tid < o) red[tid] += red[tid+o]; __syncthreads(); }
    float mu = red[0] * (1.0f/HID); __syncthreads();
    float dx=v.x-mu, dy=v.y-mu, dz=v.z-mu, dw=v.w-mu;
    red[tid] = dx*dx+dy*dy+dz*dz+dw*dw; __syncthreads();
    for (int o = 128; o > 0; o >>= 1) { if (tid < o) red[tid] += red[tid+o]; __syncthreads(); }
    float rstd = rsqrtf(red[0] * (1.0f/HID) + 1e-5f);
    float4 wv = ((const float4*)w)[tid];
    float4 bv = ((const float4*)b)[tid];
    float fx = dx*rstd*wv.x + bv.x, fy = dy*rstd*wv.y + bv.y;
    float fz = dz*rstd*wv.z + bv.z, fw = dw*rstd*wv.w + bv.w;
    if (out_full) {
        float4 f4; f4.x=fx; f4.y=fy; f4.z=fz; f4.w=fw;
        ((float4*)(out_full + (size_t)t*HID))[tid] = f4;
    }
    __half2* oh = (__half2*)(out + (size_t)t*HID);
    oh[tid*2]   = __floats2half2_rn(fx, fy);
    oh[tid*2+1] = __floats2half2_rn(fz, fw);
}

// ===== fp16 m16n8k16 GEMM with ldmatrix: 128x128 block, 64x32 warp tile =====
#define BM 128
#define BN 128
#define BKh 32
#define NSTG 3
#define ASTRH 40
#define BSTRNN 136
#define STG_H 10240
#define GSMEM (NSTG*STG_H*2)

template<int MODE>
__global__ void __launch_bounds__(256,2) mma_gemm(
        const __half* __restrict__ A, const __half* __restrict__ Bm,
        const float* __restrict__ bias, const float* __restrict__ res,
        void* __restrict__ Cv, int M, int N, int Kd) {
    extern __shared__ __half sm[];
    int tid = threadIdx.x, wid = tid>>5, lid = tid&31;
    int g = lid>>2, tg = lid&3;
    int lrow = lid & 7, grp = lid >> 3;
    int wm = (wid>>2)*64, wn = (wid&3)*32;
    int n0 = blockIdx.x*BN, m0 = blockIdx.y*BM;

    int e = 0, cnt = M;
    if (MODE >= 2) { e = blockIdx.z; cnt = g_cnt[e]; if (m0 >= cnt) return; }

    int arow = tid>>1;
    int ka   = (tid&1)*16;
    const __half* Aptr = A;
    bool av = true;
    if (MODE <= 1) {
        Aptr = A + (size_t)(m0+arow)*Kd;
    } else if (MODE == 2) {
        int t = (m0+arow < cnt) ? g_tok[e*SQ + m0 + arow] : -1;
        av = (t >= 0);
        Aptr = A + (size_t)(av ? t : 0)*Kd;
    } else {
        int rr = m0 + arow; if (rr > SQ-1) rr = SQ-1;
        Aptr = g_h1 + (size_t)(e*SQ + rr)*Kd;
    }
    const __half* Bbase = Bm;
    if (MODE >= 2) Bbase += (size_t)e * Kd * N;

    int bkr = tid>>3, bnc = (tid&7)*16;

    auto issue = [&](int kt, int s) {
        __half* As = sm + s*STG_H;
        __half* Bs = As + 5120;
        uint32_t da = sptr(&As[arow*ASTRH + ka]);
        const __half* ga = Aptr + kt*BKh + ka;
        cp16(da,      ga,     av);
        cp16(da + 16, ga + 8, av);
        if (MODE <= 1) {
            uint32_t db = sptr(&Bs[arow*ASTRH + ka]);
            const __half* gb = Bbase + (size_t)(n0+arow)*Kd + kt*BKh + ka;
            cp16(db,      gb,     true);
            cp16(db + 16, gb + 8, true);
        } else {
            uint32_t db = sptr(&Bs[bkr*BSTRNN + bnc]);
            const __half* gb = Bbase + (size_t)(kt*BKh+bkr)*N + n0 + bnc;
            cp16(db,      gb,     true);
            cp16(db + 16, gb + 8, true);
        }
        CP_COMMIT();
    };

    float acc[4][4][4] = {};
    int KT = Kd / BKh;
    issue(0, 0);
    issue(1, 1);
    int slot = 0;
    for (int kt = 0; kt < KT; kt++) {
        CP_WAIT1();
        __syncthreads();
        {
            int nk = kt + 2;
            if (nk < KT) { int ns = slot + 2; if (ns >= NSTG) ns -= NSTG; issue(nk, ns); }
            else CP_COMMIT();
        }
        const __half* as = sm + slot*STG_H;
        const __half* bs = as + 5120;
#pragma unroll
        for (int ks = 0; ks < 2; ks++) {
            int k0 = ks*16;
            uint32_t af[4][4], bf[4][2];
#pragma unroll
            for (int mi = 0; mi < 4; mi++) {
                uint32_t ad = sptr(&as[(wm + mi*16 + (grp&1)*8 + lrow)*ASTRH + k0 + (grp>>1)*8]);
                ldsm4(af[mi][0], af[mi][1], af[mi][2], af[mi][3], ad);
            }
#pragma unroll
            for (int np = 0; np < 2; np++) {
                int ni0 = np*2;
                if (MODE <= 1) {
                    uint32_t bd = sptr(&bs[(wn + (ni0 + (grp>>1))*8 + lrow)*ASTRH + k0 + (grp&1)*8]);
                    ldsm4(bf[ni0][0], bf[ni0][1], bf[ni0+1][0], bf[ni0+1][1], bd);
                } else {
                    uint32_t bd = sptr(&bs[(k0 + (grp&1)*8 + lrow)*BSTRNN + wn + (ni0 + (grp>>1))*8]);
                    ldsm4t(bf[ni0][0], bf[ni0][1], bf[ni0+1][0], bf[ni0+1][1], bd);
                }
            }
#pragma unroll
            for (int mi = 0; mi < 4; mi++)
#pragma unroll
                for (int ni = 0; ni < 4; ni++)
                    mmah(acc[mi][ni], af[mi][0], af[mi][1], af[mi][2], af[mi][3],
                         bf[ni][0], bf[ni][1]);
        }
        if (++slot == NSTG) slot = 0;
    }

    // ---- epilogue ----
#pragma unroll
    for (int mi = 0; mi < 4; mi++) {
        int r1 = m0 + wm + mi*16 + g;
        int r2 = r1 + 8;
#pragma unroll
        for (int ni = 0; ni < 4; ni++) {
            int cc = n0 + wn + ni*8 + 2*tg;
            float* a = acc[mi][ni];
            if (MODE == 0) {
                __half* C = (__half*)Cv;
                float b0 = bias[cc], b1 = bias[cc+1];
                *(__half2*)(C + (size_t)r1*N + cc) = __floats2half2_rn(a[0]+b0, a[1]+b1);
                *(__half2*)(C + (size_t)r2*N + cc) = __floats2half2_rn(a[2]+b0, a[3]+b1);
            } else if (MODE == 1) {
                float* C = (float*)Cv;
                float b0 = bias[cc], b1 = bias[cc+1];
                float v00 = a[0]+b0 + res[(size_t)r1*N + cc];
                float v01 = a[1]+b1 + res[(size_t)r1*N + cc+1];
                float v10 = a[2]+b0 + res[(size_t)r2*N + cc];
                float v11 = a[3]+b1 + res[(size_t)r2*N + cc+1];
                *(float2*)(C + (size_t)r1*N + cc) = make_float2(v00, v01);
                *(float2*)(C + (size_t)r2*N + cc) = make_float2(v10, v11);
            } else if (MODE == 2) {
                if (r1 < cnt)
                    *(__half2*)(&g_h1[(size_t)(e*SQ + r1)*FF + cc]) =
                        __floats2half2_rn(gelu_exact(a[0]), gelu_exact(a[1]));
                if (r2 < cnt)
                    *(__half2*)(&g_h1[(size_t)(e*SQ + r2)*FF + cc]) =
                        __floats2half2_rn(gelu_exact(a[2]), gelu_exact(a[3]));
            } else {
                if (r1 < cnt) {
                    int t = g_tok[e*SQ+r1], sl = g_slot[e*SQ+r1];
                    float gt = g_gate[e*SQ+r1];
                    *(float2*)(&g_y2[((size_t)t*TK+sl)*HID + cc]) =
                        make_float2(gt*a[0], gt*a[1]);
                }
                if (r2 < cnt) {
                    int t = g_tok[e*SQ+r2], sl = g_slot[e*SQ+r2];
                    float gt = g_gate[e*SQ+r2];
                    *(float2*)(&g_y2[((size_t)t*TK+sl)*HID + cc]) =
                        make_float2(gt*a[2], gt*a[3]);
                }
            }
        }
    }
}

// ===== flash attention: fp16 mma + ldmatrix + cp.async double-buffered KV =====
// Heavy q-tiles launch first (reversed order); fully-masked warp tiles skipped.
#define FBM 128
#define KVSTR 72
__global__ void __launch_bounds__(256) flash_kernel(const __half* __restrict__ qkv,
                                                    __half* __restrict__ attn) {
    int h = blockIdx.y;
    int qi = (int)gridDim.x - 1 - (int)blockIdx.x;   // heavy tiles first
    int q0 = qi * FBM;
    int tid = threadIdx.x, wid = tid>>5, lid = tid&31;
    int wm = wid*16;
    int g = lid>>2, tg = lid&3;
    int lrow = lid & 7, grp = lid >> 3;
    __shared__ __half Kv[2][64*KVSTR];
    __shared__ __half Vs[2][64*KVSTR];

    auto issue_kv = [&](int j0, int s) {
        int r = tid & 63;
        int cb = (tid >> 6) * 16;
        const __half* K = qkv + (size_t)(j0+r)*H3 + HID   + h*HD;
        const __half* V = qkv + (size_t)(j0+r)*H3 + 2*HID + h*HD;
        uint32_t dk = sptr(&Kv[s][r*KVSTR + cb]);
        cp16(dk,      K + cb,     true);
        cp16(dk + 16, K + cb + 8, true);
        uint32_t dv = sptr(&Vs[s][r*KVSTR + cb]);
        cp16(dv,      V + cb,     true);
        cp16(dv + 16, V + cb + 8, true);
        CP_COMMIT();
    };

    uint32_t qf[4][4];
    {
        const __half* Q = qkv + (size_t)(q0+wm)*H3 + h*HD;
        __half2 sc = __float2half2_rn(0.125f);
#pragma unroll
        for (int kc = 0; kc < 4; kc++) {
            int c = kc*16 + 2*tg;
            __half2 h0 = *(const __half2*)&Q[(size_t)g*H3     + c];
            __half2 h1 = *(const __half2*)&Q[(size_t)(g+8)*H3 + c];
            __half2 h2 = *(const __half2*)&Q[(size_t)g*H3     + c + 8];
            __half2 h3 = *(const __half2*)&Q[(size_t)(g+8)*H3 + c + 8];
            h0 = __hmul2(h0, sc); h1 = __hmul2(h1, sc);
            h2 = __hmul2(h2, sc); h3 = __hmul2(h3, sc);
            qf[kc][0] = *(uint32_t*)&h0; qf[kc][1] = *(uint32_t*)&h1;
            qf[kc][2] = *(uint32_t*)&h2; qf[kc][3] = *(uint32_t*)&h3;
        }
    }

    float Oc[8][4] = {};
    float m1 = -1e30f, m2 = -1e30f, l1 = 0.f, l2 = 0.f;
    int r1 = q0 + wm + g, r2 = r1 + 8;

    int ntile = (q0 + FBM) / 64;
    issue_kv(0, 0);
    for (int it = 0; it < ntile; it++) {
        int j0 = it * 64;
        if (it + 1 < ntile) { issue_kv((it+1)*64, (it+1)&1); CP_WAIT1(); }
        else                { CP_WAIT0(); }
        __syncthreads();
        const __half* kv = Kv[it&1];
        const __half* vs = Vs[it&1];

        bool act = (j0 <= q0 + wm + 15);   // warp-uniform
        if (act) {
            float Sc[8][4];
#pragma unroll
            for (int j = 0; j < 8; j++) {
                Sc[j][0] = Sc[j][1] = Sc[j][2] = Sc[j][3] = 0.f;
                uint32_t b[8];
                ldsm4(b[0], b[1], b[2], b[3], sptr(&kv[(j*8+lrow)*KVSTR + grp*8]));
                ldsm4(b[4], b[5], b[6], b[7], sptr(&kv[(j*8+lrow)*KVSTR + 32 + grp*8]));
#pragma unroll
                for (int kc = 0; kc < 4; kc++)
                    mmah(Sc[j], qf[kc][0], qf[kc][1], qf[kc][2], qf[kc][3],
                         b[kc*2], b[kc*2+1]);
            }
            if (j0 + 63 > q0 + wm) {
#pragma unroll
                for (int j = 0; j < 8; j++) {
                    int cb = j0 + j*8 + 2*tg;
                    if (cb   > r1) Sc[j][0] = -1e30f;
                    if (cb+1 > r1) Sc[j][1] = -1e30f;
                    if (cb   > r2) Sc[j][2] = -1e30f;
                    if (cb+1 > r2) Sc[j][3] = -1e30f;
                }
            }
            float mx1 = -1e30f, mx2 = -1e30f;
#pragma unroll
            for (int j = 0; j < 8; j++) {
                mx1 = fmaxf(mx1, fmaxf(Sc[j][0], Sc[j][1]));
                mx2 = fmaxf(mx2, fmaxf(Sc[j][2], Sc[j][3]));
            }
            mx1 = fmaxf(mx1, __shfl_xor_sync(0xffffffffu, mx1, 1));
            mx1 = fmaxf(mx1, __shfl_xor_sync(0xffffffffu, mx1, 2));
            mx2 = fmaxf(mx2, __shfl_xor_sync(0xffffffffu, mx2, 1));
            mx2 = fmaxf(mx2, __shfl_xor_sync(0xffffffffu, mx2, 2));
            float nm1 = fmaxf(m1, mx1), nm2 = fmaxf(m2, mx2);
            float al1 = __expf(m1 - nm1), al2 = __expf(m2 - nm2);
            float s1 = 0.f, s2 = 0.f;
#pragma unroll
            for (int j = 0; j < 8; j++) {
                Sc[j][0] = __expf(Sc[j][0] - nm1);
                Sc[j][1] = __expf(Sc[j][1] - nm1);
                Sc[j][2] = __expf(Sc[j][2] - nm2);
                Sc[j][3] = __expf(Sc[j][3] - nm2);
                s1 += Sc[j][0] + Sc[j][1];
                s2 += Sc[j][2] + Sc[j][3];
            }
            s1 += __shfl_xor_sync(0xffffffffu, s1, 1);
            s1 += __shfl_xor_sync(0xffffffffu, s1, 2);
            s2 += __shfl_xor_sync(0xffffffffu, s2, 1);
            s2 += __shfl_xor_sync(0xffffffffu, s2, 2);
            l1 = l1*al1 + s1; l2 = l2*al2 + s2;
            m1 = nm1; m2 = nm2;
#pragma unroll
            for (int jd = 0; jd < 8; jd++) {
                Oc[jd][0] *= al1; Oc[jd][1] *= al1;
                Oc[jd][2] *= al2; Oc[jd][3] *= al2;
            }
#pragma unroll
            for (int kc = 0; kc < 4; kc++) {
                uint32_t a0 = f2h2(Sc[2*kc  ][0], Sc[2*kc  ][1]);
                uint32_t a1 = f2h2(Sc[2*kc  ][2], Sc[2*kc  ][3]);
                uint32_t a2 = f2h2(Sc[2*kc+1][0], Sc[2*kc+1][1]);
                uint32_t a3 = f2h2(Sc[2*kc+1][2], Sc[2*kc+1][3]);
#pragma unroll
                for (int jp = 0; jp < 4; jp++) {
                    int jd0 = jp*2;
                    uint32_t b0, b1, b2, b3;
                    uint32_t vd = sptr(&vs[(kc*16 + (grp&1)*8 + lrow)*KVSTR + (jd0 + (grp>>1))*8]);
                    ldsm4t(b0, b1, b2, b3, vd);
                    mmah(Oc[jd0],   a0, a1, a2, a3, b0, b1);
                    mmah(Oc[jd0+1], a0, a1, a2, a3, b2, b3);
                }
            }
        }
        __syncthreads();
    }

    float inv1 = 1.f / l1, inv2 = 1.f / l2;
#pragma unroll
    for (int jd = 0; jd < 8; jd++) {
        int c = h*HD + jd*8 + 2*tg;
        *(__half2*)(attn + (size_t)r1*HID + c) =
            __floats2half2_rn(Oc[jd][0]*inv1, Oc[jd][1]*inv1);
        *(__half2*)(attn + (size_t)r2*HID + c) =
            __floats2half2_rn(Oc[jd][2]*inv2, Oc[jd][3]*inv2);
    }
}

// ---------------- router (full-precision hn2) ----------------
__global__ void router_kernel(const float* __restrict__ hn2, const float* __restrict__ rw) {
    int t = blockIdx.x, tid = threadIdx.x;
    __shared__ float part[NE][256];
    float loc[NE] = {};
    for (int hh = tid; hh < HID; hh += 256) {
        float xv = hn2[(size_t)t*HID + hh];
#pragma unroll
        for (int e = 0; e < NE; e++) loc[e] += xv * rw[e*HID + hh];
    }
#pragma unroll
    for (int e = 0; e < NE; e++) part[e][tid] = loc[e];
    __syncthreads();
    for (int o = 128; o > 0; o >>= 1) {
        if (tid < o)
#pragma unroll
            for (int e = 0; e < NE; e++) part[e][tid] += part[e][tid+o];
        __syncthreads();
    }
    if (tid == 0) {
        float lg[NE], mx = -1e30f;
#pragma unroll
        for (int e = 0; e < NE; e++) { lg[e] = part[e][0]; mx = fmaxf(mx, lg[e]); }
        float s = 0.f;
#pragma unroll
        for (int e = 0; e < NE; e++) { lg[e] = expf(lg[e]-mx); s += lg[e]; }
        float inv = 1.0f/s;
#pragma unroll
        for (int e = 0; e < NE; e++) lg[e] *= inv;
        int i0 = 0; float v0 = lg[0];
#pragma unroll
        for (int e = 1; e < NE; e++) if (lg[e] > v0) { v0 = lg[e]; i0 = e; }
        int i1 = -1; float v1 = -1e30f;
#pragma unroll
        for (int e = 0; e < NE; e++) if (e != i0 && lg[e] > v1) { v1 = lg[e]; i1 = e; }
        g_topi[t*TK+0] = i0; g_topw[t*TK+0] = v0;
        g_topi[t*TK+1] = i1; g_topw[t*TK+1] = v1;
    }
}

// ---------------- deterministic expert lists ----------------
__global__ void build_lists_kernel() {
    int e = blockIdx.x, tid = threadIdx.x;
    const int CH = SQ / 256;
    int ids[CH], slots[CH]; float gs[CH];
    int loc = 0;
    for (int c = 0; c < CH; c++) {
        int t = tid*CH + c;
        if (g_topi[t*TK+0] == e)      { ids[loc]=t; slots[loc]=0; gs[loc]=g_topw[t*TK+0]; loc++; }
        else if (g_topi[t*TK+1] == e) { ids[loc]=t; slots[loc]=1; gs[loc]=g_topw[t*TK+1]; loc++; }
    }
    __shared__ int sc[256];
    sc[tid] = loc; __syncthreads();
    for (int o = 1; o < 256; o <<= 1) {
        int v = (tid >= o) ? sc[tid-o] : 0;
        __syncthreads();
        sc[tid] += v;
        __syncthreads();
    }
    int off = sc[tid] - loc;
    for (int c = 0; c < loc; c++) {
        g_tok [e*SQ + off + c] = ids[c];
        g_slot[e*SQ + off + c] = slots[c];
        g_gate[e*SQ + off + c] = gs[c];
    }
    if (tid == 255) g_cnt[e] = sc[255];
}

// ---------------- out = x1 + y2[:,0] + y2[:,1] ----------------
__global__ void final_kernel(float* __restrict__ out) {
    int idx = blockIdx.x * 256 + threadIdx.x;
    int t = idx / HID, hh = idx % HID;
    out[idx] = g_x1[idx] + g_y2[((size_t)t*TK)*HID + hh] + g_y2[((size_t)t*TK + 1)*HID + hh];
}

// ---------------- launch ----------------
extern "C" void kernel_launch(void* const* d_in, const int* in_sizes, int n_in,
                              void* d_out, int out_size) {
    (void)in_sizes; (void)n_in; (void)out_size;
    const float* x          = (const float*)d_in[0];
    const float* ln1_w      = (const float*)d_in[1];
    const float* ln1_b      = (const float*)d_in[2];
    const float* in_proj_w  = (const float*)d_in[3];
    const float* in_proj_b  = (const float*)d_in[4];
    const float* out_proj_w = (const float*)d_in[5];
    const float* out_proj_b = (const float*)d_in[6];
    const float* ln2_w      = (const float*)d_in[7];
    const float* ln2_b      = (const float*)d_in[8];
    const float* router_w   = (const float*)d_in[9];
    const float* w1         = (const float*)d_in[10];
    const float* w2         = (const float*)d_in[11];
    float* out = (float*)d_out;

    __half *hn, *qkv, *attn, *hn2, *wqkv, *wout, *w1h, *w2h;
    float *x1, *hn2f;
    cudaGetSymbolAddress((void**)&hn,   g_hn);
    cudaGetSymbolAddress((void**)&qkv,  g_qkv);
    cudaGetSymbolAddress((void**)&attn, g_attn);
    cudaGetSymbolAddress((void**)&x1,   g_x1);
    cudaGetSymbolAddress((void**)&hn2,  g_hn2);
    cudaGetSymbolAddress((void**)&hn2f, g_hn2f);
    cudaGetSymbolAddress((void**)&wqkv, g_wqkv);
    cudaGetSymbolAddress((void**)&wout, g_wout);
    cudaGetSymbolAddress((void**)&w1h,  g_w1h);
    cudaGetSymbolAddress((void**)&w2h,  g_w2h);

    cudaFuncSetAttribute(mma_gemm<0>, cudaFuncAttributeMaxDynamicSharedMemorySize, GSMEM);
    cudaFuncSetAttribute(mma_gemm<1>, cudaFuncAttributeMaxDynamicSharedMemorySize, GSMEM);
    cudaFuncSetAttribute(mma_gemm<2>, cudaFuncAttributeMaxDynamicSharedMemorySize, GSMEM);
    cudaFuncSetAttribute(mma_gemm<3>, cudaFuncAttributeMaxDynamicSharedMemorySize, GSMEM);

    cvt_kernel<<<(H3*HID/8+255)/256, 256>>>(in_proj_w, wqkv, H3*HID);
    cvt_kernel<<<(HID*HID/8+255)/256, 256>>>(out_proj_w, wout, HID*HID);
    cvt_kernel<<<(NE*HID*FF/8+255)/256, 256>>>(w1, w1h, NE*HID*FF);
    cvt_kernel<<<(NE*FF*HID/8+255)/256, 256>>>(w2, w2h, NE*FF*HID);

    ln_kernel<<<SQ, 256>>>(x, ln1_w, ln1_b, hn, nullptr);
    mma_gemm<0><<<dim3(H3/BN, SQ/BM), 256, GSMEM>>>(hn, wqkv, in_proj_b, nullptr, qkv, SQ, H3, HID);
    flash_kernel<<<dim3(SQ/FBM, NH), 256>>>(qkv, attn);
    mma_gemm<1><<<dim3(HID/BN, SQ/BM), 256, GSMEM>>>(attn, wout, out_proj_b, x, x1, SQ, HID, HID);
    ln_kernel<<<SQ, 256>>>(x1, ln2_w, ln2_b, hn2, hn2f);
    router_kernel<<<SQ, 256>>>(hn2f, router_w);
    build_lists_kernel<<<NE, 256>>>();
    mma_gemm<2><<<dim3(FF/BN, SQ/BM, NE), 256, GSMEM>>>(hn2, w1h, nullptr, nullptr, nullptr, SQ, FF, HID);
    mma_gemm<3><<<dim3(HID/BN, SQ/BM, NE), 256, GSMEM>>>(nullptr, w2h, nullptr, nullptr, nullptr, SQ, HID, FF);
    final_kernel<<<(SQ*HID)/256, 256>>>(out);
}

// round 13
// speedup vs baseline: 2.2103x; 1.0352x over previous
#include <cuda_runtime.h>
#include <cuda_fp16.h>
#include <math.h>
#include <stdint.h>

#define SQ   2048
#define HID  1024
#define NH   16
#define HD   64
#define H3   3072
#define NE   8
#define TK   2
#define FF   2048

// ---------------- scratch ----------------
__device__ __half g_hn  [SQ*HID];
__device__ __half g_qkv [SQ*H3];
__device__ __half g_attn[SQ*HID];
__device__ float  g_x1  [SQ*HID];
__device__ __half g_hn2 [SQ*HID];
__device__ int    g_topi[SQ*TK];
__device__ float  g_topw[SQ*TK];
__device__ int    g_tok [NE*SQ];
__device__ float  g_gate[NE*SQ];
__device__ int    g_slot[NE*SQ];
__device__ int    g_cnt [NE];
__device__ __half g_h1  [(size_t)NE*SQ*FF];
__device__ float  g_y2  [SQ*TK*HID];
__device__ __half g_wqkv[H3*HID];
__device__ __half g_wout[HID*HID];
__device__ __half g_w1h [(size_t)NE*HID*FF];
__device__ __half g_w2h [(size_t)NE*FF*HID];

// ---------------- helpers ----------------
__device__ __forceinline__ void mmah(float* c, uint32_t a0, uint32_t a1, uint32_t a2,
                                     uint32_t a3, uint32_t b0, uint32_t b1) {
    asm volatile("mma.sync.aligned.m16n8k16.row.col.f32.f16.f16.f32 "
        "{%0,%1,%2,%3},{%4,%5,%6,%7},{%8,%9},{%0,%1,%2,%3};\n"
        : "+f"(c[0]), "+f"(c[1]), "+f"(c[2]), "+f"(c[3])
        : "r"(a0), "r"(a1), "r"(a2), "r"(a3), "r"(b0), "r"(b1));
}
__device__ __forceinline__ void ldsm4(uint32_t& r0, uint32_t& r1, uint32_t& r2,
                                      uint32_t& r3, uint32_t addr) {
    asm volatile("ldmatrix.sync.aligned.m8n8.x4.shared.b16 {%0,%1,%2,%3}, [%4];"
        : "=r"(r0), "=r"(r1), "=r"(r2), "=r"(r3) : "r"(addr));
}
__device__ __forceinline__ void ldsm4t(uint32_t& r0, uint32_t& r1, uint32_t& r2,
                                       uint32_t& r3, uint32_t addr) {
    asm volatile("ldmatrix.sync.aligned.m8n8.x4.trans.shared.b16 {%0,%1,%2,%3}, [%4];"
        : "=r"(r0), "=r"(r1), "=r"(r2), "=r"(r3) : "r"(addr));
}
__device__ __forceinline__ uint32_t f2h2(float a, float b) {
    __half2 h = __floats2half2_rn(a, b); return *(uint32_t*)&h;
}
__device__ __forceinline__ uint32_t sptr(const void* p) {
    return (uint32_t)__cvta_generic_to_shared(p);
}
__device__ __forceinline__ void cp16(uint32_t s, const void* g, bool v) {
    int sz = v ? 16 : 0;
    asm volatile("cp.async.cg.shared.global [%0], [%1], 16, %2;\n"
                 :: "r"(s), "l"(g), "r"(sz));
}
#define CP_COMMIT() asm volatile("cp.async.commit_group;\n")
#define CP_WAIT2()  asm volatile("cp.async.wait_group 2;\n")
#define CP_WAIT1()  asm volatile("cp.async.wait_group 1;\n")
#define CP_WAIT0()  asm volatile("cp.async.wait_group 0;\n")

__device__ __forceinline__ float gelu_exact(float x) {
    return 0.5f * x * (1.0f + erff(x * 0.70710678118654752f));
}

// ---------------- merged weight convert ----------------
#define N0 (H3*HID)
#define N1 (HID*HID)
#define N2 (NE*HID*FF)
#define NTOT (N0+N1+N2+N2)
__global__ void cvt_all_kernel(const float* __restrict__ s0, const float* __restrict__ s1,
                               const float* __restrict__ s2, const float* __restrict__ s3) {
    int i = (blockIdx.x * 256 + threadIdx.x) * 8;
    if (i >= NTOT) return;
    const float* s; __half* d; int off;
    if (i < N0)                { s = s0; d = g_wqkv; off = i; }
    else if (i < N0+N1)        { s = s1; d = g_wout; off = i - N0; }
    else if (i < N0+N1+N2)     { s = s2; d = g_w1h;  off = i - N0 - N1; }
    else                       { s = s3; d = g_w2h;  off = i - N0 - N1 - N2; }
    float4 v0 = *(const float4*)(s + off);
    float4 v1 = *(const float4*)(s + off + 4);
    __half2 h0 = __floats2half2_rn(v0.x, v0.y);
    __half2 h1 = __floats2half2_rn(v0.z, v0.w);
    __half2 h2 = __floats2half2_rn(v1.x, v1.y);
    __half2 h3 = __floats2half2_rn(v1.z, v1.w);
    uint4 o;
    o.x = *(uint32_t*)&h0; o.y = *(uint32_t*)&h1;
    o.z = *(uint32_t*)&h2; o.w = *(uint32_t*)&h3;
    *(uint4*)(d + off) = o;
}

// ---------------- layernorm (half out); optional fused router top-2 ----------
template<bool ROUTER>
__global__ void ln_kernel(const float* __restrict__ x, const float* __restrict__ w,
                          const float* __restrict__ b, __half* __restrict__ out,
                          const float* __restrict__ rw) {
    int t = blockIdx.x, tid = threadIdx.x;
    float4 v = ((const float4*)(x + (size_t)t*HID))[tid];
    __shared__ float red[256];
    red[tid] = v.x+v.y+v.z+v.w; __syncthreads();
    for (int o = 128; o > 0; o >>= 1) { if (tid < o) red[tid] += red[tid+o]; __syncthreads(); }
    float mu = red[0] * (1.0f/HID); __syncthreads();
    float dx=v.x-mu, dy=v.y-mu, dz=v.z-mu, dw=v.w-mu;
    red[tid] = dx*dx+dy*dy+dz*dz+dw*dw; __syncthreads();
    for (int o = 128; o > 0; o >>= 1) { if (tid < o) red[tid] += red[tid+o]; __syncthreads(); }
    float rstd = rsqrtf(red[0] * (1.0f/HID) + 1e-5f);
    float4 wv = ((const float4*)w)[tid];
    float4 bv = ((const float4*)b)[tid];
    float fx = dx*rstd*wv.x + bv.x, fy = dy*rstd*wv.y + bv.y;
    float fz = dz*rstd*wv.z + bv.z, fw = dw*rstd*wv.w + bv.w;
    __half2* oh = (__half2*)(out + (size_t)t*HID);
    oh[tid*2]   = __floats2half2_rn(fx, fy);
    oh[tid*2+1] = __floats2half2_rn(fz, fw);

    if (ROUTER) {
        __shared__ float part[NE][256];
        int c0 = tid*4;
#pragma unroll
        for (int e = 0; e < NE; e++) {
            const float* r = rw + e*HID + c0;
            part[e][tid] = fx*r[0] + fy*r[1] + fz*r[2] + fw*r[3];
        }
        __syncthreads();
        for (int o = 128; o > 0; o >>= 1) {
            if (tid < o)
#pragma unroll
                for (int e = 0; e < NE; e++) part[e][tid] += part[e][tid+o];
            __syncthreads();
        }
        if (tid == 0) {
            float lg[NE], mx = -1e30f;
#pragma unroll
            for (int e = 0; e < NE; e++) { lg[e] = part[e][0]; mx = fmaxf(mx, lg[e]); }
            float s = 0.f;
#pragma unroll
            for (int e = 0; e < NE; e++) { lg[e] = expf(lg[e]-mx); s += lg[e]; }
            float inv = 1.0f/s;
#pragma unroll
            for (int e = 0; e < NE; e++) lg[e] *= inv;
            int i0 = 0; float v0 = lg[0];
#pragma unroll
            for (int e = 1; e < NE; e++) if (lg[e] > v0) { v0 = lg[e]; i0 = e; }
            int i1 = -1; float v1 = -1e30f;
#pragma unroll
            for (int e = 0; e < NE; e++) if (e != i0 && lg[e] > v1) { v1 = lg[e]; i1 = e; }
            g_topi[t*TK+0] = i0; g_topw[t*TK+0] = v0;
            g_topi[t*TK+1] = i1; g_topw[t*TK+1] = v1;
        }
    }
}

// ===== fp16 m16n8k16 GEMM, ldmatrix, 4-stage cp.async (3 loads in flight) =====
#define BM 128
#define BN 128
#define BKh 32
#define NSTG 4
#define ASTRH 40
#define BSTRNN 136
#define STG_H 10240
#define GSMEM (NSTG*STG_H*2)

template<int MODE>
__global__ void __launch_bounds__(256,2) mma_gemm(
        const __half* __restrict__ A, const __half* __restrict__ Bm,
        const float* __restrict__ bias, const float* __restrict__ res,
        void* __restrict__ Cv, int M, int N, int Kd) {
    extern __shared__ __half sm[];
    int tid = threadIdx.x, wid = tid>>5, lid = tid&31;
    int g = lid>>2, tg = lid&3;
    int lrow = lid & 7, grp = lid >> 3;
    int wm = (wid>>2)*64, wn = (wid&3)*32;
    int n0 = blockIdx.x*BN, m0 = blockIdx.y*BM;

    int e = 0, cnt = M;
    if (MODE >= 2) { e = blockIdx.z; cnt = g_cnt[e]; if (m0 >= cnt) return; }

    int arow = tid>>1;
    int ka   = (tid&1)*16;
    const __half* Aptr = A;
    bool av = true;
    if (MODE <= 1) {
        Aptr = A + (size_t)(m0+arow)*Kd;
    } else if (MODE == 2) {
        int t = (m0+arow < cnt) ? g_tok[e*SQ + m0 + arow] : -1;
        av = (t >= 0);
        Aptr = A + (size_t)(av ? t : 0)*Kd;
    } else {
        int rr = m0 + arow; if (rr > SQ-1) rr = SQ-1;
        Aptr = g_h1 + (size_t)(e*SQ + rr)*Kd;
    }
    const __half* Bbase = Bm;
    if (MODE >= 2) Bbase += (size_t)e * Kd * N;

    int bkr = tid>>3, bnc = (tid&7)*16;

    auto issue = [&](int kt, int s) {
        __half* As = sm + s*STG_H;
        __half* Bs = As + 5120;
        uint32_t da = sptr(&As[arow*ASTRH + ka]);
        const __half* ga = Aptr + kt*BKh + ka;
        cp16(da,      ga,     av);
        cp16(da + 16, ga + 8, av);
        if (MODE <= 1) {
            uint32_t db = sptr(&Bs[arow*ASTRH + ka]);
            const __half* gb = Bbase + (size_t)(n0+arow)*Kd + kt*BKh + ka;
            cp16(db,      gb,     true);
            cp16(db + 16, gb + 8, true);
        } else {
            uint32_t db = sptr(&Bs[bkr*BSTRNN + bnc]);
            const __half* gb = Bbase + (size_t)(kt*BKh+bkr)*N + n0 + bnc;
            cp16(db,      gb,     true);
            cp16(db + 16, gb + 8, true);
        }
        CP_COMMIT();
    };

    float acc[4][4][4] = {};
    int KT = Kd / BKh;
    issue(0, 0);
    issue(1, 1);
    issue(2, 2);
    int slot = 0;
    for (int kt = 0; kt < KT; kt++) {
        CP_WAIT2();
        __syncthreads();
        {
            int nk = kt + 3;
            if (nk < KT) { int ns = slot + 3; if (ns >= NSTG) ns -= NSTG; issue(nk, ns); }
            else CP_COMMIT();
        }
        const __half* as = sm + slot*STG_H;
        const __half* bs = as + 5120;
#pragma unroll
        for (int ks = 0; ks < 2; ks++) {
            int k0 = ks*16;
            uint32_t af[4][4], bf[4][2];
#pragma unroll
            for (int mi = 0; mi < 4; mi++) {
                uint32_t ad = sptr(&as[(wm + mi*16 + (grp&1)*8 + lrow)*ASTRH + k0 + (grp>>1)*8]);
                ldsm4(af[mi][0], af[mi][1], af[mi][2], af[mi][3], ad);
            }
#pragma unroll
            for (int np = 0; np < 2; np++) {
                int ni0 = np*2;
                if (MODE <= 1) {
                    uint32_t bd = sptr(&bs[(wn + (ni0 + (grp>>1))*8 + lrow)*ASTRH + k0 + (grp&1)*8]);
                    ldsm4(bf[ni0][0], bf[ni0][1], bf[ni0+1][0], bf[ni0+1][1], bd);
                } else {
                    uint32_t bd = sptr(&bs[(k0 + (grp&1)*8 + lrow)*BSTRNN + wn + (ni0 + (grp>>1))*8]);
                    ldsm4t(bf[ni0][0], bf[ni0][1], bf[ni0+1][0], bf[ni0+1][1], bd);
                }
            }
#pragma unroll
            for (int mi = 0; mi < 4; mi++)
#pragma unroll
                for (int ni = 0; ni < 4; ni++)
                    mmah(acc[mi][ni], af[mi][0], af[mi][1], af[mi][2], af[mi][3],
                         bf[ni][0], bf[ni][1]);
        }
        if (++slot == NSTG) slot = 0;
    }

    // ---- epilogue ----
#pragma unroll
    for (int mi = 0; mi < 4; mi++) {
        int r1 = m0 + wm + mi*16 + g;
        int r2 = r1 + 8;
#pragma unroll
        for (int ni = 0; ni < 4; ni++) {
            int cc = n0 + wn + ni*8 + 2*tg;
            float* a = acc[mi][ni];
            if (MODE == 0) {
                __half* C = (__half*)Cv;
                float b0 = bias[cc], b1 = bias[cc+1];
                *(__half2*)(C + (size_t)r1*N + cc) = __floats2half2_rn(a[0]+b0, a[1]+b1);
                *(__half2*)(C + (size_t)r2*N + cc) = __floats2half2_rn(a[2]+b0, a[3]+b1);
            } else if (MODE == 1) {
                float* C = (float*)Cv;
                float b0 = bias[cc], b1 = bias[cc+1];
                float v00 = a[0]+b0 + res[(size_t)r1*N + cc];
                float v01 = a[1]+b1 + res[(size_t)r1*N + cc+1];
                float v10 = a[2]+b0 + res[(size_t)r2*N + cc];
                float v11 = a[3]+b1 + res[(size_t)r2*N + cc+1];
                *(float2*)(C + (size_t)r1*N + cc) = make_float2(v00, v01);
                *(float2*)(C + (size_t)r2*N + cc) = make_float2(v10, v11);
            } else if (MODE == 2) {
                if (r1 < cnt)
                    *(__half2*)(&g_h1[(size_t)(e*SQ + r1)*FF + cc]) =
                        __floats2half2_rn(gelu_exact(a[0]), gelu_exact(a[1]));
                if (r2 < cnt)
                    *(__half2*)(&g_h1[(size_t)(e*SQ + r2)*FF + cc]) =
                        __floats2half2_rn(gelu_exact(a[2]), gelu_exact(a[3]));
            } else {
                if (r1 < cnt) {
                    int t = g_tok[e*SQ+r1], sl = g_slot[e*SQ+r1];
                    float gt = g_gate[e*SQ+r1];
                    *(float2*)(&g_y2[((size_t)t*TK+sl)*HID + cc]) =
                        make_float2(gt*a[0], gt*a[1]);
                }
                if (r2 < cnt) {
                    int t = g_tok[e*SQ+r2], sl = g_slot[e*SQ+r2];
                    float gt = g_gate[e*SQ+r2];
                    *(float2*)(&g_y2[((size_t)t*TK+sl)*HID + cc]) =
                        make_float2(gt*a[2], gt*a[3]);
                }
            }
        }
    }
}

// ===== flash: fp16 mma + ldmatrix + 3-buffer cp.async KV, 1 sync/iter =====
#define FBM 128
#define KVSTR 72
#define FSTG_H (64*KVSTR)          // halves per KV buffer
#define FSMEM (3*2*FSTG_H*2)       // 3 stages x (K+V) x halves x 2B = 55296
__global__ void __launch_bounds__(256) flash_kernel(const __half* __restrict__ qkv,
                                                    __half* __restrict__ attn) {
    extern __shared__ __half fsm[];
    __half* KvB = fsm;               // [3][FSTG_H]
    __half* VsB = fsm + 3*FSTG_H;    // [3][FSTG_H]
    int h = blockIdx.y;
    int qi = (int)gridDim.x - 1 - (int)blockIdx.x;   // heavy tiles first
    int q0 = qi * FBM;
    int tid = threadIdx.x, wid = tid>>5, lid = tid&31;
    int wm = wid*16;
    int g = lid>>2, tg = lid&3;
    int lrow = lid & 7, grp = lid >> 3;

    auto issue_kv = [&](int j0, int s) {
        int r = tid & 63;
        int cb = (tid >> 6) * 16;
        const __half* K = qkv + (size_t)(j0+r)*H3 + HID   + h*HD;
        const __half* V = qkv + (size_t)(j0+r)*H3 + 2*HID + h*HD;
        uint32_t dk = sptr(&KvB[s*FSTG_H + r*KVSTR + cb]);
        cp16(dk,      K + cb,     true);
        cp16(dk + 16, K + cb + 8, true);
        uint32_t dv = sptr(&VsB[s*FSTG_H + r*KVSTR + cb]);
        cp16(dv,      V + cb,     true);
        cp16(dv + 16, V + cb + 8, true);
        CP_COMMIT();
    };

    issue_kv(0, 0);

    uint32_t qf[4][4];
    {
        const __half* Q = qkv + (size_t)(q0+wm)*H3 + h*HD;
        __half2 sc = __float2half2_rn(0.125f);
#pragma unroll
        for (int kc = 0; kc < 4; kc++) {
            int c = kc*16 + 2*tg;
            __half2 h0 = *(const __half2*)&Q[(size_t)g*H3     + c];
            __half2 h1 = *(const __half2*)&Q[(size_t)(g+8)*H3 + c];
            __half2 h2 = *(const __half2*)&Q[(size_t)g*H3     + c + 8];
            __half2 h3 = *(const __half2*)&Q[(size_t)(g+8)*H3 + c + 8];
            h0 = __hmul2(h0, sc); h1 = __hmul2(h1, sc);
            h2 = __hmul2(h2, sc); h3 = __hmul2(h3, sc);
            qf[kc][0] = *(uint32_t*)&h0; qf[kc][1] = *(uint32_t*)&h1;
            qf[kc][2] = *(uint32_t*)&h2; qf[kc][3] = *(uint32_t*)&h3;
        }
    }

    float Oc[8][4] = {};
    float m1 = -1e30f, m2 = -1e30f, l1 = 0.f, l2 = 0.f;
    int r1 = q0 + wm + g, r2 = r1 + 8;

    int ntile = (q0 + FBM) / 64;
    int slot = 0;
    for (int it = 0; it < ntile; it++) {
        int j0 = it * 64;
        if (it + 1 < ntile) {
            int ns = slot + 1; if (ns == 3) ns = 0;
            issue_kv((it+1)*64, ns);
            CP_WAIT1();
        } else {
            CP_WAIT0();
        }
        __syncthreads();
        const __half* kv = KvB + slot*FSTG_H;
        const __half* vs = VsB + slot*FSTG_H;

        bool act = (j0 <= q0 + wm + 15);
        if (act) {
            float Sc[8][4];
#pragma unroll
            for (int j = 0; j < 8; j++) {
                Sc[j][0] = Sc[j][1] = Sc[j][2] = Sc[j][3] = 0.f;
                uint32_t b[8];
                ldsm4(b[0], b[1], b[2], b[3], sptr(&kv[(j*8+lrow)*KVSTR + grp*8]));
                ldsm4(b[4], b[5], b[6], b[7], sptr(&kv[(j*8+lrow)*KVSTR + 32 + grp*8]));
#pragma unroll
                for (int kc = 0; kc < 4; kc++)
                    mmah(Sc[j], qf[kc][0], qf[kc][1], qf[kc][2], qf[kc][3],
                         b[kc*2], b[kc*2+1]);
            }
            if (j0 + 63 > q0 + wm) {
#pragma unroll
                for (int j = 0; j < 8; j++) {
                    int cb = j0 + j*8 + 2*tg;
                    if (cb   > r1) Sc[j][0] = -1e30f;
                    if (cb+1 > r1) Sc[j][1] = -1e30f;
                    if (cb   > r2) Sc[j][2] = -1e30f;
                    if (cb+1 > r2) Sc[j][3] = -1e30f;
                }
            }
            float mx1 = -1e30f, mx2 = -1e30f;
#pragma unroll
            for (int j = 0; j < 8; j++) {
                mx1 = fmaxf(mx1, fmaxf(Sc[j][0], Sc[j][1]));
                mx2 = fmaxf(mx2, fmaxf(Sc[j][2], Sc[j][3]));
            }
            mx1 = fmaxf(mx1, __shfl_xor_sync(0xffffffffu, mx1, 1));
            mx1 = fmaxf(mx1, __shfl_xor_sync(0xffffffffu, mx1, 2));
            mx2 = fmaxf(mx2, __shfl_xor_sync(0xffffffffu, mx2, 1));
            mx2 = fmaxf(mx2, __shfl_xor_sync(0xffffffffu, mx2, 2));
            float nm1 = fmaxf(m1, mx1), nm2 = fmaxf(m2, mx2);
            float al1 = __expf(m1 - nm1), al2 = __expf(m2 - nm2);
            float s1 = 0.f, s2 = 0.f;
#pragma unroll
            for (int j = 0; j < 8; j++) {
                Sc[j][0] = __expf(Sc[j][0] - nm1);
                Sc[j][1] = __expf(Sc[j][1] - nm1);
                Sc[j][2] = __expf(Sc[j][2] - nm2);
                Sc[j][3] = __expf(Sc[j][3] - nm2);
                s1 += Sc[j][0] + Sc[j][1];
                s2 += Sc[j][2] + Sc[j][3];
            }
            s1 += __shfl_xor_sync(0xffffffffu, s1, 1);
            s1 += __shfl_xor_sync(0xffffffffu, s1, 2);
            s2 += __shfl_xor_sync(0xffffffffu, s2, 1);
            s2 += __shfl_xor_sync(0xffffffffu, s2, 2);
            l1 = l1*al1 + s1; l2 = l2*al2 + s2;
            m1 = nm1; m2 = nm2;
#pragma unroll
            for (int jd = 0; jd < 8; jd++) {
                Oc[jd][0] *= al1; Oc[jd][1] *= al1;
                Oc[jd][2] *= al2; Oc[jd][3] *= al2;
            }
#pragma unroll
            for (int kc = 0; kc < 4; kc++) {
                uint32_t a0 = f2h2(Sc[2*kc  ][0], Sc[2*kc  ][1]);
                uint32_t a1 = f2h2(Sc[2*kc  ][2], Sc[2*kc  ][3]);
                uint32_t a2 = f2h2(Sc[2*kc+1][0], Sc[2*kc+1][1]);
                uint32_t a3 = f2h2(Sc[2*kc+1][2], Sc[2*kc+1][3]);
#pragma unroll
                for (int jp = 0; jp < 4; jp++) {
                    int jd0 = jp*2;
                    uint32_t b0, b1, b2, b3;
                    uint32_t vd = sptr(&vs[(kc*16 + (grp&1)*8 + lrow)*KVSTR + (jd0 + (grp>>1))*8]);
                    ldsm4t(b0, b1, b2, b3, vd);
                    mmah(Oc[jd0],   a0, a1, a2, a3, b0, b1);
                    mmah(Oc[jd0+1], a0, a1, a2, a3, b2, b3);
                }
            }
        }
        if (++slot == 3) slot = 0;
    }

    float inv1 = 1.f / l1, inv2 = 1.f / l2;
#pragma unroll
    for (int jd = 0; jd < 8; jd++) {
        int c = h*HD + jd*8 + 2*tg;
        *(__half2*)(attn + (size_t)r1*HID + c) =
            __floats2half2_rn(Oc[jd][0]*inv1, Oc[jd][1]*inv1);
        *(__half2*)(attn + (size_t)r2*HID + c) =
            __floats2half2_rn(Oc[jd][2]*inv2, Oc[jd][3]*inv2);
    }
}

// ---------------- deterministic expert lists ----------------
__global__ void build_lists_kernel() {
    int e = blockIdx.x, tid = threadIdx.x;
    const int CH = SQ / 256;
    int ids[CH], slots[CH]; float gs[CH];
    int loc = 0;
    for (int c = 0; c < CH; c++) {
        int t = tid*CH + c;
        if (g_topi[t*TK+0] == e)      { ids[loc]=t; slots[loc]=0; gs[loc]=g_topw[t*TK+0]; loc++; }
        else if (g_topi[t*TK+1] == e) { ids[loc]=t; slots[loc]=1; gs[loc]=g_topw[t*TK+1]; loc++; }
    }
    __shared__ int sc[256];
    sc[tid] = loc; __syncthreads();
    for (int o = 1; o < 256; o <<= 1) {
        int v = (tid >= o) ? sc[tid-o] : 0;
        __syncthreads();
        sc[tid] += v;
        __syncthreads();
    }
    int off = sc[tid] - loc;
    for (int c = 0; c < loc; c++) {
        g_tok [e*SQ + off + c] = ids[c];
        g_slot[e*SQ + off + c] = slots[c];
        g_gate[e*SQ + off + c] = gs[c];
    }
    if (tid == 255) g_cnt[e] = sc[255];
}

// ---------------- out = x1 + y2[:,0] + y2[:,1] ----------------
__global__ void final_kernel(float* __restrict__ out) {
    int idx = blockIdx.x * 256 + threadIdx.x;
    int t = idx / HID, hh = idx % HID;
    out[idx] = g_x1[idx] + g_y2[((size_t)t*TK)*HID + hh] + g_y2[((size_t)t*TK + 1)*HID + hh];
}

// ---------------- launch ----------------
extern "C" void kernel_launch(void* const* d_in, const int* in_sizes, int n_in,
                              void* d_out, int out_size) {
    (void)in_sizes; (void)n_in; (void)out_size;
    const float* x          = (const float*)d_in[0];
    const float* ln1_w      = (const float*)d_in[1];
    const float* ln1_b      = (const float*)d_in[2];
    const float* in_proj_w  = (const float*)d_in[3];
    const float* in_proj_b  = (const float*)d_in[4];
    const float* out_proj_w = (const float*)d_in[5];
    const float* out_proj_b = (const float*)d_in[6];
    const float* ln2_w      = (const float*)d_in[7];
    const float* ln2_b      = (const float*)d_in[8];
    const float* router_w   = (const float*)d_in[9];
    const float* w1         = (const float*)d_in[10];
    const float* w2         = (const float*)d_in[11];
    float* out = (float*)d_out;

    __half *hn, *qkv, *attn, *hn2, *wqkv, *wout, *w1h, *w2h;
    float *x1;
    cudaGetSymbolAddress((void**)&hn,   g_hn);
    cudaGetSymbolAddress((void**)&qkv,  g_qkv);
    cudaGetSymbolAddress((void**)&attn, g_attn);
    cudaGetSymbolAddress((void**)&x1,   g_x1);
    cudaGetSymbolAddress((void**)&hn2,  g_hn2);
    cudaGetSymbolAddress((void**)&wqkv, g_wqkv);
    cudaGetSymbolAddress((void**)&wout, g_wout);
    cudaGetSymbolAddress((void**)&w1h,  g_w1h);
    cudaGetSymbolAddress((void**)&w2h,  g_w2h);

    cudaFuncSetAttribute(mma_gemm<0>, cudaFuncAttributeMaxDynamicSharedMemorySize, GSMEM);
    cudaFuncSetAttribute(mma_gemm<1>, cudaFuncAttributeMaxDynamicSharedMemorySize, GSMEM);
    cudaFuncSetAttribute(mma_gemm<2>, cudaFuncAttributeMaxDynamicSharedMemorySize, GSMEM);
    cudaFuncSetAttribute(mma_gemm<3>, cudaFuncAttributeMaxDynamicSharedMemorySize, GSMEM);
    cudaFuncSetAttribute(flash_kernel, cudaFuncAttributeMaxDynamicSharedMemorySize, FSMEM);

    cvt_all_kernel<<<(NTOT/8+255)/256, 256>>>(in_proj_w, out_proj_w, w1, w2);

    ln_kernel<false><<<SQ, 256>>>(x, ln1_w, ln1_b, hn, nullptr);
    mma_gemm<0><<<dim3(H3/BN, SQ/BM), 256, GSMEM>>>(hn, wqkv, in_proj_b, nullptr, qkv, SQ, H3, HID);
    flash_kernel<<<dim3(SQ/FBM, NH), 256, FSMEM>>>(qkv, attn);
    mma_gemm<1><<<dim3(HID/BN, SQ/BM), 256, GSMEM>>>(attn, wout, out_proj_b, x, x1, SQ, HID, HID);
    ln_kernel<true><<<SQ, 256>>>(x1, ln2_w, ln2_b, hn2, router_w);
    build_lists_kernel<<<NE, 256>>>();
    mma_gemm<2><<<dim3(FF/BN, SQ/BM, NE), 256, GSMEM>>>(hn2, w1h, nullptr, nullptr, nullptr, SQ, FF, HID);
    mma_gemm<3><<<dim3(HID/BN, SQ/BM, NE), 256, GSMEM>>>(nullptr, w2h, nullptr, nullptr, nullptr, SQ, HID, FF);
    final_kernel<<<(SQ*HID)/256, 256>>>(out);
}

// round 14
// speedup vs baseline: 2.2192x; 1.0040x over previous
#include <cuda_runtime.h>
#include <cuda_fp16.h>
#include <math.h>
#include <stdint.h>

#define SQ   2048
#define HID  1024
#define NH   16
#define HD   64
#define H3   3072
#define NE   8
#define TK   2
#define FF   2048

// ---------------- scratch ----------------
__device__ __half g_hn  [SQ*HID];
__device__ __half g_qkv [SQ*H3];
__device__ __half g_attn[SQ*HID];
__device__ float  g_x1  [SQ*HID];
__device__ __half g_hn2 [SQ*HID];
__device__ int    g_topi[SQ*TK];
__device__ float  g_topw[SQ*TK];
__device__ int    g_tok [NE*SQ];
__device__ float  g_gate[NE*SQ];
__device__ int    g_slot[NE*SQ];
__device__ int    g_cnt [NE];
__device__ __half g_h1  [(size_t)NE*SQ*FF];
__device__ float  g_y2  [SQ*TK*HID];
__device__ __half g_wqkv[H3*HID];
__device__ __half g_wout[HID*HID];
__device__ __half g_w1h [(size_t)NE*HID*FF];
__device__ __half g_w2h [(size_t)NE*FF*HID];

// ---------------- helpers ----------------
__device__ __forceinline__ void mmah(float* c, uint32_t a0, uint32_t a1, uint32_t a2,
                                     uint32_t a3, uint32_t b0, uint32_t b1) {
    asm volatile("mma.sync.aligned.m16n8k16.row.col.f32.f16.f16.f32 "
        "{%0,%1,%2,%3},{%4,%5,%6,%7},{%8,%9},{%0,%1,%2,%3};\n"
        : "+f"(c[0]), "+f"(c[1]), "+f"(c[2]), "+f"(c[3])
        : "r"(a0), "r"(a1), "r"(a2), "r"(a3), "r"(b0), "r"(b1));
}
__device__ __forceinline__ void ldsm4(uint32_t& r0, uint32_t& r1, uint32_t& r2,
                                      uint32_t& r3, uint32_t addr) {
    asm volatile("ldmatrix.sync.aligned.m8n8.x4.shared.b16 {%0,%1,%2,%3}, [%4];"
        : "=r"(r0), "=r"(r1), "=r"(r2), "=r"(r3) : "r"(addr));
}
__device__ __forceinline__ void ldsm4t(uint32_t& r0, uint32_t& r1, uint32_t& r2,
                                       uint32_t& r3, uint32_t addr) {
    asm volatile("ldmatrix.sync.aligned.m8n8.x4.trans.shared.b16 {%0,%1,%2,%3}, [%4];"
        : "=r"(r0), "=r"(r1), "=r"(r2), "=r"(r3) : "r"(addr));
}
__device__ __forceinline__ uint32_t f2h2(float a, float b) {
    __half2 h = __floats2half2_rn(a, b); return *(uint32_t*)&h;
}
__device__ __forceinline__ uint32_t sptr(const void* p) {
    return (uint32_t)__cvta_generic_to_shared(p);
}
__device__ __forceinline__ void cp16(uint32_t s, const void* g, bool v) {
    int sz = v ? 16 : 0;
    asm volatile("cp.async.cg.shared.global [%0], [%1], 16, %2;\n"
                 :: "r"(s), "l"(g), "r"(sz));
}
#define CP_COMMIT() asm volatile("cp.async.commit_group;\n")
#define CP_WAIT2()  asm volatile("cp.async.wait_group 2;\n")
#define CP_WAIT1()  asm volatile("cp.async.wait_group 1;\n")
#define CP_WAIT0()  asm volatile("cp.async.wait_group 0;\n")

__device__ __forceinline__ float gelu_exact(float x) {
    return 0.5f * x * (1.0f + erff(x * 0.70710678118654752f));
}

// ---------------- merged weight convert ----------------
#define N0 (H3*HID)
#define N1 (HID*HID)
#define N2 (NE*HID*FF)
#define NTOT (N0+N1+N2+N2)
__global__ void cvt_all_kernel(const float* __restrict__ s0, const float* __restrict__ s1,
                               const float* __restrict__ s2, const float* __restrict__ s3) {
    int i = (blockIdx.x * 256 + threadIdx.x) * 8;
    if (i >= NTOT) return;
    const float* s; __half* d; int off;
    if (i < N0)                { s = s0; d = g_wqkv; off = i; }
    else if (i < N0+N1)        { s = s1; d = g_wout; off = i - N0; }
    else if (i < N0+N1+N2)     { s = s2; d = g_w1h;  off = i - N0 - N1; }
    else                       { s = s3; d = g_w2h;  off = i - N0 - N1 - N2; }
    float4 v0 = *(const float4*)(s + off);
    float4 v1 = *(const float4*)(s + off + 4);
    __half2 h0 = __floats2half2_rn(v0.x, v0.y);
    __half2 h1 = __floats2half2_rn(v0.z, v0.w);
    __half2 h2 = __floats2half2_rn(v1.x, v1.y);
    __half2 h3 = __floats2half2_rn(v1.z, v1.w);
    uint4 o;
    o.x = *(uint32_t*)&h0; o.y = *(uint32_t*)&h1;
    o.z = *(uint32_t*)&h2; o.w = *(uint32_t*)&h3;
    *(uint4*)(d + off) = o;
}

// ---------------- layernorm (half out); optional fused router top-2 ----------
template<bool ROUTER>
__global__ void ln_kernel(const float* __restrict__ x, const float* __restrict__ w,
                          const float* __restrict__ b, __half* __restrict__ out,
                          const float* __restrict__ rw) {
    int t = blockIdx.x, tid = threadIdx.x;
    float4 v = ((const float4*)(x + (size_t)t*HID))[tid];
    __shared__ float red[256];
    red[tid] = v.x+v.y+v.z+v.w; __syncthreads();
    for (int o = 128; o > 0; o >>= 1) { if (tid < o) red[tid] += red[tid+o]; __syncthreads(); }
    float mu = red[0] * (1.0f/HID); __syncthreads();
    float dx=v.x-mu, dy=v.y-mu, dz=v.z-mu, dw=v.w-mu;
    red[tid] = dx*dx+dy*dy+dz*dz+dw*dw; __syncthreads();
    for (int o = 128; o > 0; o >>= 1) { if (tid < o) red[tid] += red[tid+o]; __syncthreads(); }
    float rstd = rsqrtf(red[0] * (1.0f/HID) + 1e-5f);
    float4 wv = ((const float4*)w)[tid];
    float4 bv = ((const float4*)b)[tid];
    float fx = dx*rstd*wv.x + bv.x, fy = dy*rstd*wv.y + bv.y;
    float fz = dz*rstd*wv.z + bv.z, fw = dw*rstd*wv.w + bv.w;
    __half2* oh = (__half2*)(out + (size_t)t*HID);
    oh[tid*2]   = __floats2half2_rn(fx, fy);
    oh[tid*2+1] = __floats2half2_rn(fz, fw);

    if (ROUTER) {
        __shared__ float part[NE][256];
        int c0 = tid*4;
#pragma unroll
        for (int e = 0; e < NE; e++) {
            const float* r = rw + e*HID + c0;
            part[e][tid] = fx*r[0] + fy*r[1] + fz*r[2] + fw*r[3];
        }
        __syncthreads();
        for (int o = 128; o > 0; o >>= 1) {
            if (tid < o)
#pragma unroll
                for (int e = 0; e < NE; e++) part[e][tid] += part[e][tid+o];
            __syncthreads();
        }
        if (tid == 0) {
            float lg[NE], mx = -1e30f;
#pragma unroll
            for (int e = 0; e < NE; e++) { lg[e] = part[e][0]; mx = fmaxf(mx, lg[e]); }
            float s = 0.f;
#pragma unroll
            for (int e = 0; e < NE; e++) { lg[e] = expf(lg[e]-mx); s += lg[e]; }
            float inv = 1.0f/s;
#pragma unroll
            for (int e = 0; e < NE; e++) lg[e] *= inv;
            int i0 = 0; float v0 = lg[0];
#pragma unroll
            for (int e = 1; e < NE; e++) if (lg[e] > v0) { v0 = lg[e]; i0 = e; }
            int i1 = -1; float v1 = -1e30f;
#pragma unroll
            for (int e = 0; e < NE; e++) if (e != i0 && lg[e] > v1) { v1 = lg[e]; i1 = e; }
            g_topi[t*TK+0] = i0; g_topw[t*TK+0] = v0;
            g_topi[t*TK+1] = i1; g_topw[t*TK+1] = v1;
        }
    }
}

// ===== fp16 m16n8k16 GEMM, ldmatrix, 4-stage cp.async (3 loads in flight) =====
#define BM 128
#define BN 128
#define BKh 32
#define NSTG 4
#define ASTRH 40
#define BSTRNN 136
#define STG_H 10240
#define GSMEM (NSTG*STG_H*2)

template<int MODE>
__global__ void __launch_bounds__(256,2) mma_gemm(
        const __half* __restrict__ A, const __half* __restrict__ Bm,
        const float* __restrict__ bias, const float* __restrict__ res,
        void* __restrict__ Cv, int M, int N, int Kd) {
    extern __shared__ __half sm[];
    int tid = threadIdx.x, wid = tid>>5, lid = tid&31;
    int g = lid>>2, tg = lid&3;
    int lrow = lid & 7, grp = lid >> 3;
    int wm = (wid>>2)*64, wn = (wid&3)*32;
    int n0 = blockIdx.x*BN, m0 = blockIdx.y*BM;

    int e = 0, cnt = M;
    if (MODE >= 2) { e = blockIdx.z; cnt = g_cnt[e]; if (m0 >= cnt) return; }

    int arow = tid>>1;
    int ka   = (tid&1)*16;
    const __half* Aptr = A;
    bool av = true;
    if (MODE <= 1) {
        Aptr = A + (size_t)(m0+arow)*Kd;
    } else if (MODE == 2) {
        int t = (m0+arow < cnt) ? g_tok[e*SQ + m0 + arow] : -1;
        av = (t >= 0);
        Aptr = A + (size_t)(av ? t : 0)*Kd;
    } else {
        int rr = m0 + arow; if (rr > SQ-1) rr = SQ-1;
        Aptr = g_h1 + (size_t)(e*SQ + rr)*Kd;
    }
    const __half* Bbase = Bm;
    if (MODE >= 2) Bbase += (size_t)e * Kd * N;

    int bkr = tid>>3, bnc = (tid&7)*16;

    auto issue = [&](int kt, int s) {
        __half* As = sm + s*STG_H;
        __half* Bs = As + 5120;
        uint32_t da = sptr(&As[arow*ASTRH + ka]);
        const __half* ga = Aptr + kt*BKh + ka;
        cp16(da,      ga,     av);
        cp16(da + 16, ga + 8, av);
        if (MODE <= 1) {
            uint32_t db = sptr(&Bs[arow*ASTRH + ka]);
            const __half* gb = Bbase + (size_t)(n0+arow)*Kd + kt*BKh + ka;
            cp16(db,      gb,     true);
            cp16(db + 16, gb + 8, true);
        } else {
            uint32_t db = sptr(&Bs[bkr*BSTRNN + bnc]);
            const __half* gb = Bbase + (size_t)(kt*BKh+bkr)*N + n0 + bnc;
            cp16(db,      gb,     true);
            cp16(db + 16, gb + 8, true);
        }
        CP_COMMIT();
    };

    float acc[4][4][4] = {};
    int KT = Kd / BKh;
    issue(0, 0);
    issue(1, 1);
    issue(2, 2);
    int slot = 0;
    for (int kt = 0; kt < KT; kt++) {
        CP_WAIT2();
        __syncthreads();
        {
            int nk = kt + 3;
            if (nk < KT) { int ns = slot + 3; if (ns >= NSTG) ns -= NSTG; issue(nk, ns); }
            else CP_COMMIT();
        }
        const __half* as = sm + slot*STG_H;
        const __half* bs = as + 5120;
#pragma unroll
        for (int ks = 0; ks < 2; ks++) {
            int k0 = ks*16;
            uint32_t af[4][4], bf[4][2];
#pragma unroll
            for (int mi = 0; mi < 4; mi++) {
                uint32_t ad = sptr(&as[(wm + mi*16 + (grp&1)*8 + lrow)*ASTRH + k0 + (grp>>1)*8]);
                ldsm4(af[mi][0], af[mi][1], af[mi][2], af[mi][3], ad);
            }
#pragma unroll
            for (int np = 0; np < 2; np++) {
                int ni0 = np*2;
                if (MODE <= 1) {
                    uint32_t bd = sptr(&bs[(wn + (ni0 + (grp>>1))*8 + lrow)*ASTRH + k0 + (grp&1)*8]);
                    ldsm4(bf[ni0][0], bf[ni0][1], bf[ni0+1][0], bf[ni0+1][1], bd);
                } else {
                    uint32_t bd = sptr(&bs[(k0 + (grp&1)*8 + lrow)*BSTRNN + wn + (ni0 + (grp>>1))*8]);
                    ldsm4t(bf[ni0][0], bf[ni0][1], bf[ni0+1][0], bf[ni0+1][1], bd);
                }
            }
#pragma unroll
            for (int mi = 0; mi < 4; mi++)
#pragma unroll
                for (int ni = 0; ni < 4; ni++)
                    mmah(acc[mi][ni], af[mi][0], af[mi][1], af[mi][2], af[mi][3],
                         bf[ni][0], bf[ni][1]);
        }
        if (++slot == NSTG) slot = 0;
    }

    // ---- epilogue ----
#pragma unroll
    for (int mi = 0; mi < 4; mi++) {
        int r1 = m0 + wm + mi*16 + g;
        int r2 = r1 + 8;
#pragma unroll
        for (int ni = 0; ni < 4; ni++) {
            int cc = n0 + wn + ni*8 + 2*tg;
            float* a = acc[mi][ni];
            if (MODE == 0) {
                __half* C = (__half*)Cv;
                float b0 = bias[cc], b1 = bias[cc+1];
                *(__half2*)(C + (size_t)r1*N + cc) = __floats2half2_rn(a[0]+b0, a[1]+b1);
                *(__half2*)(C + (size_t)r2*N + cc) = __floats2half2_rn(a[2]+b0, a[3]+b1);
            } else if (MODE == 1) {
                float* C = (float*)Cv;
                float b0 = bias[cc], b1 = bias[cc+1];
                float v00 = a[0]+b0 + res[(size_t)r1*N + cc];
                float v01 = a[1]+b1 + res[(size_t)r1*N + cc+1];
                float v10 = a[2]+b0 + res[(size_t)r2*N + cc];
                float v11 = a[3]+b1 + res[(size_t)r2*N + cc+1];
                *(float2*)(C + (size_t)r1*N + cc) = make_float2(v00, v01);
                *(float2*)(C + (size_t)r2*N + cc) = make_float2(v10, v11);
            } else if (MODE == 2) {
                if (r1 < cnt)
                    *(__half2*)(&g_h1[(size_t)(e*SQ + r1)*FF + cc]) =
                        __floats2half2_rn(gelu_exact(a[0]), gelu_exact(a[1]));
                if (r2 < cnt)
                    *(__half2*)(&g_h1[(size_t)(e*SQ + r2)*FF + cc]) =
                        __floats2half2_rn(gelu_exact(a[2]), gelu_exact(a[3]));
            } else {
                if (r1 < cnt) {
                    int t = g_tok[e*SQ+r1], sl = g_slot[e*SQ+r1];
                    float gt = g_gate[e*SQ+r1];
                    *(float2*)(&g_y2[((size_t)t*TK+sl)*HID + cc]) =
                        make_float2(gt*a[0], gt*a[1]);
                }
                if (r2 < cnt) {
                    int t = g_tok[e*SQ+r2], sl = g_slot[e*SQ+r2];
                    float gt = g_gate[e*SQ+r2];
                    *(float2*)(&g_y2[((size_t)t*TK+sl)*HID + cc]) =
                        make_float2(gt*a[2], gt*a[3]);
                }
            }
        }
    }
}

// ===== flash: fp16 mma + ldmatrix + 3-buffer cp.async KV, 1 sync/iter =====
#define FBM 128
#define KVSTR 72
#define FSTG_H (64*KVSTR)          // halves per KV buffer
#define FSMEM (3*2*FSTG_H*2)       // 3 stages x (K+V) x halves x 2B = 55296
__global__ void __launch_bounds__(256) flash_kernel(const __half* __restrict__ qkv,
                                                    __half* __restrict__ attn) {
    extern __shared__ __half fsm[];
    __half* KvB = fsm;               // [3][FSTG_H]
    __half* VsB = fsm + 3*FSTG_H;    // [3][FSTG_H]
    int h = blockIdx.y;
    int qi = (int)gridDim.x - 1 - (int)blockIdx.x;   // heavy tiles first
    int q0 = qi * FBM;
    int tid = threadIdx.x, wid = tid>>5, lid = tid&31;
    int wm = wid*16;
    int g = lid>>2, tg = lid&3;
    int lrow = lid & 7, grp = lid >> 3;

    auto issue_kv = [&](int j0, int s) {
        int r = tid & 63;
        int cb = (tid >> 6) * 16;
        const __half* K = qkv + (size_t)(j0+r)*H3 + HID   + h*HD;
        const __half* V = qkv + (size_t)(j0+r)*H3 + 2*HID + h*HD;
        uint32_t dk = sptr(&KvB[s*FSTG_H + r*KVSTR + cb]);
        cp16(dk,      K + cb,     true);
        cp16(dk + 16, K + cb + 8, true);
        uint32_t dv = sptr(&VsB[s*FSTG_H + r*KVSTR + cb]);
        cp16(dv,      V + cb,     true);
        cp16(dv + 16, V + cb + 8, true);
        CP_COMMIT();
    };

    issue_kv(0, 0);

    uint32_t qf[4][4];
    {
        const __half* Q = qkv + (size_t)(q0+wm)*H3 + h*HD;
        __half2 sc = __float2half2_rn(0.125f);
#pragma unroll
        for (int kc = 0; kc < 4; kc++) {
            int c = kc*16 + 2*tg;
            __half2 h0 = *(const __half2*)&Q[(size_t)g*H3     + c];
            __half2 h1 = *(const __half2*)&Q[(size_t)(g+8)*H3 + c];
            __half2 h2 = *(const __half2*)&Q[(size_t)g*H3     + c + 8];
            __half2 h3 = *(const __half2*)&Q[(size_t)(g+8)*H3 + c + 8];
            h0 = __hmul2(h0, sc); h1 = __hmul2(h1, sc);
            h2 = __hmul2(h2, sc); h3 = __hmul2(h3, sc);
            qf[kc][0] = *(uint32_t*)&h0; qf[kc][1] = *(uint32_t*)&h1;
            qf[kc][2] = *(uint32_t*)&h2; qf[kc][3] = *(uint32_t*)&h3;
        }
    }

    float Oc[8][4] = {};
    float m1 = -1e30f, m2 = -1e30f, l1 = 0.f, l2 = 0.f;
    int r1 = q0 + wm + g, r2 = r1 + 8;

    int ntile = (q0 + FBM) / 64;
    int slot = 0;
    for (int it = 0; it < ntile; it++) {
        int j0 = it * 64;
        if (it + 1 < ntile) {
            int ns = slot + 1; if (ns == 3) ns = 0;
            issue_kv((it+1)*64, ns);
            CP_WAIT1();
        } else {
            CP_WAIT0();
        }
        __syncthreads();
        const __half* kv = KvB + slot*FSTG_H;
        const __half* vs = VsB + slot*FSTG_H;

        bool act = (j0 <= q0 + wm + 15);
        if (act) {
            float Sc[8][4];
#pragma unroll
            for (int j = 0; j < 8; j++) {
                Sc[j][0] = Sc[j][1] = Sc[j][2] = Sc[j][3] = 0.f;
                uint32_t b[8];
                ldsm4(b[0], b[1], b[2], b[3], sptr(&kv[(j*8+lrow)*KVSTR + grp*8]));
                ldsm4(b[4], b[5], b[6], b[7], sptr(&kv[(j*8+lrow)*KVSTR + 32 + grp*8]));
#pragma unroll
                for (int kc = 0; kc < 4; kc++)
                    mmah(Sc[j], qf[kc][0], qf[kc][1], qf[kc][2], qf[kc][3],
                         b[kc*2], b[kc*2+1]);
            }
            if (j0 + 63 > q0 + wm) {
#pragma unroll
                for (int j = 0; j < 8; j++) {
                    int cb = j0 + j*8 + 2*tg;
                    if (cb   > r1) Sc[j][0] = -1e30f;
                    if (cb+1 > r1) Sc[j][1] = -1e30f;
                    if (cb   > r2) Sc[j][2] = -1e30f;
                    if (cb+1 > r2) Sc[j][3] = -1e30f;
                }
            }
            float mx1 = -1e30f, mx2 = -1e30f;
#pragma unroll
            for (int j = 0; j < 8; j++) {
                mx1 = fmaxf(mx1, fmaxf(Sc[j][0], Sc[j][1]));
                mx2 = fmaxf(mx2, fmaxf(Sc[j][2], Sc[j][3]));
            }
            mx1 = fmaxf(mx1, __shfl_xor_sync(0xffffffffu, mx1, 1));
            mx1 = fmaxf(mx1, __shfl_xor_sync(0xffffffffu, mx1, 2));
            mx2 = fmaxf(mx2, __shfl_xor_sync(0xffffffffu, mx2, 1));
            mx2 = fmaxf(mx2, __shfl_xor_sync(0xffffffffu, mx2, 2));
            float nm1 = fmaxf(m1, mx1), nm2 = fmaxf(m2, mx2);
            float al1 = __expf(m1 - nm1), al2 = __expf(m2 - nm2);
            float s1 = 0.f, s2 = 0.f;
#pragma unroll
            for (int j = 0; j < 8; j++) {
                Sc[j][0] = __expf(Sc[j][0] - nm1);
                Sc[j][1] = __expf(Sc[j][1] - nm1);
                Sc[j][2] = __expf(Sc[j][2] - nm2);
                Sc[j][3] = __expf(Sc[j][3] - nm2);
                s1 += Sc[j][0] + Sc[j][1];
                s2 += Sc[j][2] + Sc[j][3];
            }
            s1 += __shfl_xor_sync(0xffffffffu, s1, 1);
            s1 += __shfl_xor_sync(0xffffffffu, s1, 2);
            s2 += __shfl_xor_sync(0xffffffffu, s2, 1);
            s2 += __shfl_xor_sync(0xffffffffu, s2, 2);
            l1 = l1*al1 + s1; l2 = l2*al2 + s2;
            m1 = nm1; m2 = nm2;
#pragma unroll
            for (int jd = 0; jd < 8; jd++) {
                Oc[jd][0] *= al1; Oc[jd][1] *= al1;
                Oc[jd][2] *= al2; Oc[jd][3] *= al2;
            }
#pragma unroll
            for (int kc = 0; kc < 4; kc++) {
                uint32_t a0 = f2h2(Sc[2*kc  ][0], Sc[2*kc  ][1]);
                uint32_t a1 = f2h2(Sc[2*kc  ][2], Sc[2*kc  ][3]);
                uint32_t a2 = f2h2(Sc[2*kc+1][0], Sc[2*kc+1][1]);
                uint32_t a3 = f2h2(Sc[2*kc+1][2], Sc[2*kc+1][3]);
#pragma unroll
                for (int jp = 0; jp < 4; jp++) {
                    int jd0 = jp*2;
                    uint32_t b0, b1, b2, b3;
                    uint32_t vd = sptr(&vs[(kc*16 + (grp&1)*8 + lrow)*KVSTR + (jd0 + (grp>>1))*8]);
                    ldsm4t(b0, b1, b2, b3, vd);
                    mmah(Oc[jd0],   a0, a1, a2, a3, b0, b1);
                    mmah(Oc[jd0+1], a0, a1, a2, a3, b2, b3);
                }
            }
        }
        if (++slot == 3) slot = 0;
    }

    float inv1 = 1.f / l1, inv2 = 1.f / l2;
#pragma unroll
    for (int jd = 0; jd < 8; jd++) {
        int c = h*HD + jd*8 + 2*tg;
        *(__half2*)(attn + (size_t)r1*HID + c) =
            __floats2half2_rn(Oc[jd][0]*inv1, Oc[jd][1]*inv1);
        *(__half2*)(attn + (size_t)r2*HID + c) =
            __floats2half2_rn(Oc[jd][2]*inv2, Oc[jd][3]*inv2);
    }
}

// ---------------- deterministic expert lists ----------------
__global__ void build_lists_kernel() {
    int e = blockIdx.x, tid = threadIdx.x;
    const int CH = SQ / 256;
    int ids[CH], slots[CH]; float gs[CH];
    int loc = 0;
    for (int c = 0; c < CH; c++) {
        int t = tid*CH + c;
        if (g_topi[t*TK+0] == e)      { ids[loc]=t; slots[loc]=0; gs[loc]=g_topw[t*TK+0]; loc++; }
        else if (g_topi[t*TK+1] == e) { ids[loc]=t; slots[loc]=1; gs[loc]=g_topw[t*TK+1]; loc++; }
    }
    __shared__ int sc[256];
    sc[tid] = loc; __syncthreads();
    for (int o = 1; o < 256; o <<= 1) {
        int v = (tid >= o) ? sc[tid-o] : 0;
        __syncthreads();
        sc[tid] += v;
        __syncthreads();
    }
    int off = sc[tid] - loc;
    for (int c = 0; c < loc; c++) {
        g_tok [e*SQ + off + c] = ids[c];
        g_slot[e*SQ + off + c] = slots[c];
        g_gate[e*SQ + off + c] = gs[c];
    }
    if (tid == 255) g_cnt[e] = sc[255];
}

// ---------------- out = x1 + y2[:,0] + y2[:,1] ----------------
__global__ void final_kernel(float* __restrict__ out) {
    int idx = blockIdx.x * 256 + threadIdx.x;
    int t = idx / HID, hh = idx % HID;
    out[idx] = g_x1[idx] + g_y2[((size_t)t*TK)*HID + hh] + g_y2[((size_t)t*TK + 1)*HID + hh];
}

// ---------------- launch ----------------
extern "C" void kernel_launch(void* const* d_in, const int* in_sizes, int n_in,
                              void* d_out, int out_size) {
    (void)in_sizes; (void)n_in; (void)out_size;
    const float* x          = (const float*)d_in[0];
    const float* ln1_w      = (const float*)d_in[1];
    const float* ln1_b      = (const float*)d_in[2];
    const float* in_proj_w  = (const float*)d_in[3];
    const float* in_proj_b  = (const float*)d_in[4];
    const float* out_proj_w = (const float*)d_in[5];
    const float* out_proj_b = (const float*)d_in[6];
    const float* ln2_w      = (const float*)d_in[7];
    const float* ln2_b      = (const float*)d_in[8];
    const float* router_w   = (const float*)d_in[9];
    const float* w1         = (const float*)d_in[10];
    const float* w2         = (const float*)d_in[11];
    float* out = (float*)d_out;

    __half *hn, *qkv, *attn, *hn2, *wqkv, *wout, *w1h, *w2h;
    float *x1;
    cudaGetSymbolAddress((void**)&hn,   g_hn);
    cudaGetSymbolAddress((void**)&qkv,  g_qkv);
    cudaGetSymbolAddress((void**)&attn, g_attn);
    cudaGetSymbolAddress((void**)&x1,   g_x1);
    cudaGetSymbolAddress((void**)&hn2,  g_hn2);
    cudaGetSymbolAddress((void**)&wqkv, g_wqkv);
    cudaGetSymbolAddress((void**)&wout, g_wout);
    cudaGetSymbolAddress((void**)&w1h,  g_w1h);
    cudaGetSymbolAddress((void**)&w2h,  g_w2h);

    cudaFuncSetAttribute(mma_gemm<0>, cudaFuncAttributeMaxDynamicSharedMemorySize, GSMEM);
    cudaFuncSetAttribute(mma_gemm<1>, cudaFuncAttributeMaxDynamicSharedMemorySize, GSMEM);
    cudaFuncSetAttribute(mma_gemm<2>, cudaFuncAttributeMaxDynamicSharedMemorySize, GSMEM);
    cudaFuncSetAttribute(mma_gemm<3>, cudaFuncAttributeMaxDynamicSharedMemorySize, GSMEM);
    cudaFuncSetAttribute(flash_kernel, cudaFuncAttributeMaxDynamicSharedMemorySize, FSMEM);

    cvt_all_kernel<<<(NTOT/8+255)/256, 256>>>(in_proj_w, out_proj_w, w1, w2);

    ln_kernel<false><<<SQ, 256>>>(x, ln1_w, ln1_b, hn, nullptr);
    mma_gemm<0><<<dim3(H3/BN, SQ/BM), 256, GSMEM>>>(hn, wqkv, in_proj_b, nullptr, qkv, SQ, H3, HID);
    flash_kernel<<<dim3(SQ/FBM, NH), 256, FSMEM>>>(qkv, attn);
    mma_gemm<1><<<dim3(HID/BN, SQ/BM), 256, GSMEM>>>(attn, wout, out_proj_b, x, x1, SQ, HID, HID);
    ln_kernel<true><<<SQ, 256>>>(x1, ln2_w, ln2_b, hn2, router_w);
    build_lists_kernel<<<NE, 256>>>();
    mma_gemm<2><<<dim3(FF/BN, SQ/BM, NE), 256, GSMEM>>>(hn2, w1h, nullptr, nullptr, nullptr, SQ, FF, HID);
    mma_gemm<3><<<dim3(HID/BN, SQ/BM, NE), 256, GSMEM>>>(nullptr, w2h, nullptr, nullptr, nullptr, SQ, HID, FF);
    final_kernel<<<(SQ*HID)/256, 256>>>(out);
}